// round 6
// baseline (speedup 1.0000x reference)
#include <cuda_runtime.h>
#include <cuda_bf16.h>
#include <math.h>

#define Bq 2
#define Nq 2048
#define Fq 128
#define Mq 8
#define Uq 64
#define NM (Nq * Mq)            // 16384 rows of A'
#define OUTSZ (Bq * Nq * Mq * Uq)

#define JC 64                   // j per stage
#define NSTAGE (Nq / JC)        // 32

// smem per buffer: A' 64 rows x 64 j bf16 (row stride 144B) hi+lo, B 64 u x 64 j hi+lo
#define SA 144
#define AH_OFF 0
#define AL_OFF (AH_OFF + 64 * SA)       //  9216
#define BH_OFF (AL_OFF + 64 * SA)       // 18432
#define BL_OFF (BH_OFF + 64 * SA)       // 27648
#define BUF_SZ (BL_OFF + 64 * SA)       // 36864
#define SMEM_MAIN (2 * BUF_SZ)          // 73728

// device scratch (allocation-free rule)
__device__ float g_beta[Bq * Nq * Uq];
__device__ float g_alpha[OUTSZ];
__device__ unsigned short g_bTh[Bq * Uq * Nq];   // betaT hi bf16 [b][u][n]
__device__ unsigned short g_bTl[Bq * Uq * Nq];   // betaT lo bf16

__device__ __forceinline__ unsigned smem_u32(const void* p) {
    unsigned r;
    asm("{ .reg .u64 t; cvta.to.shared.u64 t, %1; cvt.u32.u64 %0, t; }"
        : "=r"(r) : "l"(p));
    return r;
}
__device__ __forceinline__ unsigned cvt_bf16x2(float lo_elem, float hi_elem) {
    unsigned r;   // low 16 bits <- lo_elem, high <- hi_elem
    asm("cvt.rn.bf16x2.f32 %0, %1, %2;" : "=r"(r) : "f"(hi_elem), "f"(lo_elem));
    return r;
}
__device__ __forceinline__ float bf_lo_f(unsigned h) { return __uint_as_float(h << 16); }
__device__ __forceinline__ float bf_hi_f(unsigned h) { return __uint_as_float(h & 0xffff0000u); }

#define LDSM4(r0, r1, r2, r3, addr) \
    asm volatile("ldmatrix.sync.aligned.m8n8.x4.shared.b16 {%0,%1,%2,%3}, [%4];" \
                 : "=r"(r0), "=r"(r1), "=r"(r2), "=r"(r3) : "r"(addr))

__device__ __forceinline__ void mma_bf16(float* c, const unsigned* a, const unsigned* b) {
    asm volatile(
        "mma.sync.aligned.m16n8k16.row.col.f32.bf16.bf16.f32 "
        "{%0,%1,%2,%3}, {%4,%5,%6,%7}, {%8,%9}, {%0,%1,%2,%3};"
        : "+f"(c[0]), "+f"(c[1]), "+f"(c[2]), "+f"(c[3])
        : "r"(a[0]), "r"(a[1]), "r"(a[2]), "r"(a[3]), "r"(b[0]), "r"(b[1]));
}

// ---------------------------------------------------------------------------
// Kernel A: beta = seq @ e_w, alpha = seq @ v_w. (unchanged, works)
// ---------------------------------------------------------------------------
__global__ void __launch_bounds__(256) precompute_kernel(
        const float* __restrict__ seq,
        const float* __restrict__ e_w,
        const float* __restrict__ v_w) {
    __shared__ float sS[64][33];
    __shared__ float sW[32][68];

    const int bx = blockIdx.x;
    const int by = blockIdx.y;
    const int row0 = by * 64;

    const float* wsrc;
    int wstride, c0;
    if (bx == 0) { wsrc = e_w; wstride = Uq;      c0 = 0; }
    else         { wsrc = v_w; wstride = Mq * Uq; c0 = (bx - 1) * 64; }

    const int tid = threadIdx.x;
    const int tx = tid & 15;
    const int ty = tid >> 4;

    float acc[4][4];
#pragma unroll
    for (int r = 0; r < 4; r++)
#pragma unroll
        for (int c = 0; c < 4; c++) acc[r][c] = 0.f;

    for (int fb = 0; fb < Fq; fb += 32) {
#pragma unroll
        for (int k = 0; k < 2; k++) {
            int v = tid + k * 256;
            int r = v >> 3, fq = (v & 7) * 4;
            float4 t = *(const float4*)&seq[(row0 + r) * Fq + fb + fq];
            sS[r][fq + 0] = t.x; sS[r][fq + 1] = t.y;
            sS[r][fq + 2] = t.z; sS[r][fq + 3] = t.w;
        }
#pragma unroll
        for (int k = 0; k < 2; k++) {
            int v = tid + k * 256;
            int f = v >> 4, cq = (v & 15) * 4;
            float4 t = *(const float4*)&wsrc[(fb + f) * wstride + c0 + cq];
            *(float4*)&sW[f][cq] = t;
        }
        __syncthreads();

#pragma unroll 4
        for (int f = 0; f < 32; f++) {
            float a[4];
#pragma unroll
            for (int r = 0; r < 4; r++) a[r] = sS[ty * 4 + r][f];
            float4 b4 = *(const float4*)&sW[f][tx * 4];
            float bb[4] = {b4.x, b4.y, b4.z, b4.w};
#pragma unroll
            for (int r = 0; r < 4; r++)
#pragma unroll
                for (int c = 0; c < 4; c++)
                    acc[r][c] = fmaf(a[r], bb[c], acc[r][c]);
        }
        __syncthreads();
    }

#pragma unroll
    for (int r = 0; r < 4; r++) {
        const int bn = row0 + ty * 4 + r;
#pragma unroll
        for (int c = 0; c < 4; c++) {
            const int col = tx * 4 + c;
            if (bx == 0) g_beta[bn * Uq + col] = acc[r][c];
            else         g_alpha[bn * (Mq * Uq) + c0 + col] = acc[r][c];
        }
    }
}

// ---------------------------------------------------------------------------
// Kernel T: betaT hi/lo bf16 (unchanged, works)
// ---------------------------------------------------------------------------
__global__ void __launch_bounds__(256) betaT_kernel() {
    __shared__ float s[128][65];
    const int b  = blockIdx.y;
    const int n0 = blockIdx.x * 128;
    const int tid = threadIdx.x;

#pragma unroll
    for (int k = 0; k < 8; k++) {
        int v = tid + k * 256;
        int n = v >> 4, uq = (v & 15) * 4;
        float4 t = *(const float4*)&g_beta[((b * Nq) + n0 + n) * Uq + uq];
        s[n][uq + 0] = t.x; s[n][uq + 1] = t.y;
        s[n][uq + 2] = t.z; s[n][uq + 3] = t.w;
    }
    __syncthreads();

    const int w = tid >> 5, l = tid & 31;
#pragma unroll
    for (int r = 0; r < 8; r++) {
        int u = w * 8 + r;
        float a0 = s[4 * l + 0][u], a1 = s[4 * l + 1][u];
        float a2 = s[4 * l + 2][u], a3 = s[4 * l + 3][u];
        unsigned h01 = cvt_bf16x2(a0, a1), h23 = cvt_bf16x2(a2, a3);
        float r0 = a0 - bf_lo_f(h01), r1 = a1 - bf_hi_f(h01);
        float r2 = a2 - bf_lo_f(h23), r3 = a3 - bf_hi_f(h23);
        unsigned l01 = cvt_bf16x2(r0, r1), l23 = cvt_bf16x2(r2, r3);
        size_t idx = (size_t)(b * Uq + u) * Nq + n0 + 4 * l;
        *(uint2*)&g_bTh[idx] = make_uint2(h01, h23);
        *(uint2*)&g_bTl[idx] = make_uint2(l01, l23);
    }
}

// ---------------------------------------------------------------------------
// Kernel B (main): fused, double-buffered, 3-pass bf16 mma.
// C[(i*8+m), u] = sum_j graph[b,i,j,m] * beta[b,j,u]; out = sigmoid(C + alpha).
// Grid (256, 2): 256 row-tiles of 64 rows (= 8 i x 8 m) x batch. 256 threads.
// Warps: wr = w>>2 (2 x 32 rows), wc = w&3 (4 x 16 u). Warp tile 32 x 16.
// Per stage (JC=64): per warp 4 ks x (6 LDSM.x4 + 12 HMMA) = 48 HMMA.
// One __syncthreads per stage; LDG of stage s+1 issued before mma of stage s.
// ---------------------------------------------------------------------------
__global__ void __launch_bounds__(256, 2) multigraph_mma_kernel(
        const float* __restrict__ graph,
        float* __restrict__ out) {
    extern __shared__ __align__(16) char smem[];
    const unsigned sb = smem_u32(smem);

    const int tid = threadIdx.x;
    const int l = tid & 31;
    const int w = tid >> 5;
    const int wr = w >> 2;
    const int wc = w & 3;

    const int rt0 = blockIdx.x * 64;         // global A' row base
    const int b   = blockIdx.y;
    const int i0  = rt0 >> 3;                // graph i base (8 i per block)

    // per-thread staging decomposition (cells: 8 il x 2 mq x 32 jp)
    const int jp0 = tid & 31;
    const int mq0 = (tid >> 5) & 1;
    const int il0 = tid >> 6;                 // cell a=0
    const int jp1 = jp0, mq1 = mq0, il1 = il0 + 4;  // cell a=1 (tid+256)
    const int bu  = tid >> 3;                 // B: u for k=0 (tid<512 ok: two iters)
    const int bjq = tid & 7;

    float acc[2][2][4];
#pragma unroll
    for (int rt = 0; rt < 2; rt++)
#pragma unroll
        for (int nt = 0; nt < 2; nt++)
#pragma unroll
            for (int k = 0; k < 4; k++) acc[rt][nt][k] = 0.f;

    // ldmatrix lane addressing (same proven mapping as round 5)
    const unsigned aRow = (unsigned)(wr * 32 + (l & 15)) * SA + ((l >> 4) * 16);
    const unsigned bRow = (unsigned)(wc * 16 + (l & 7) + ((l >> 4) & 1) * 8) * SA
                        + (((l >> 3) & 1) * 16);

    const size_t gbase = ((size_t)b * Nq + i0) * Nq * Mq;
    const size_t bTb = (size_t)b * Uq * Nq;

    // staged registers
    float4 av[2], aw[2];
    uint4 bhv[2], blv[2];

    // ---- LDG stage s into registers
    auto ldg_stage = [&](int s) {
        const int j0 = s * JC;
        {
            const float* gp = graph + gbase
                + ((size_t)il0 * Nq + (j0 + 2 * jp0)) * Mq + mq0 * 4;
            av[0] = *(const float4*)gp;
            aw[0] = *(const float4*)(gp + Mq);
        }
        {
            const float* gp = graph + gbase
                + ((size_t)il1 * Nq + (j0 + 2 * jp1)) * Mq + mq1 * 4;
            av[1] = *(const float4*)gp;
            aw[1] = *(const float4*)(gp + Mq);
        }
#pragma unroll
        for (int k = 0; k < 2; k++) {
            int u = bu + k * 32;
            size_t src = bTb + (size_t)u * Nq + j0 + bjq * 8;
            bhv[k] = *(const uint4*)&g_bTh[src];
            blv[k] = *(const uint4*)&g_bTl[src];
        }
    };

    // ---- cvt + STS staged registers into buffer p
    auto sts_stage = [&](int p) {
        char* buf = smem + p * BUF_SZ;
#pragma unroll
        for (int a = 0; a < 2; a++) {
            const int il = (a ? il1 : il0), mq = (a ? mq1 : mq0), jp = (a ? jp1 : jp0);
            const float* v = (const float*)&av[a];
            const float* wv = (const float*)&aw[a];
#pragma unroll
            for (int m = 0; m < 4; m++) {
                unsigned h = cvt_bf16x2(v[m], wv[m]);
                float r0 = v[m] - bf_lo_f(h);
                float r1 = wv[m] - bf_hi_f(h);
                unsigned lo = cvt_bf16x2(r0, r1);
                unsigned off = (unsigned)(il * 8 + mq * 4 + m) * SA + jp * 4;
                *(unsigned*)(buf + AH_OFF + off) = h;
                *(unsigned*)(buf + AL_OFF + off) = lo;
            }
        }
#pragma unroll
        for (int k = 0; k < 2; k++) {
            unsigned off = (unsigned)(bu + k * 32) * SA + bjq * 16;
            *(uint4*)(buf + BH_OFF + off) = bhv[k];
            *(uint4*)(buf + BL_OFF + off) = blv[k];
        }
    };

    // ---- mma over buffer p
    auto mma_stage = [&](int p) {
        const unsigned base = sb + (unsigned)p * BUF_SZ;
#pragma unroll
        for (int ks = 0; ks < 4; ks++) {
            unsigned ah[2][4], al[2][4], bh[4], bl[4];
#pragma unroll
            for (int rt = 0; rt < 2; rt++) {
                unsigned aoff = aRow + (unsigned)rt * 16 * SA + ks * 32;
                LDSM4(ah[rt][0], ah[rt][1], ah[rt][2], ah[rt][3], base + AH_OFF + aoff);
                LDSM4(al[rt][0], al[rt][1], al[rt][2], al[rt][3], base + AL_OFF + aoff);
            }
            {
                unsigned boff = bRow + ks * 32;
                LDSM4(bh[0], bh[1], bh[2], bh[3], base + BH_OFF + boff);
                LDSM4(bl[0], bl[1], bl[2], bl[3], base + BL_OFF + boff);
            }
#pragma unroll
            for (int rt = 0; rt < 2; rt++)
#pragma unroll
                for (int nt = 0; nt < 2; nt++) {
                    mma_bf16(acc[rt][nt], ah[rt], &bh[nt * 2]);
                    mma_bf16(acc[rt][nt], al[rt], &bh[nt * 2]);
                    mma_bf16(acc[rt][nt], ah[rt], &bl[nt * 2]);
                }
        }
    };

    // prologue
    ldg_stage(0);
    sts_stage(0);

#pragma unroll 1
    for (int s = 0; s < NSTAGE; s++) {
        __syncthreads();                 // buf[s&1] ready; buf[(s+1)&1] free
        if (s + 1 < NSTAGE) ldg_stage(s + 1);
        mma_stage(s & 1);
        if (s + 1 < NSTAGE) sts_stage((s + 1) & 1);
    }

    // fused epilogue: + alpha, sigmoid, store
#pragma unroll
    for (int rt = 0; rt < 2; rt++) {
        const int r0 = rt0 + wr * 32 + rt * 16 + (l >> 2);
#pragma unroll
        for (int nt = 0; nt < 2; nt++) {
            const int u = wc * 16 + nt * 8 + (l & 3) * 2;
            const size_t idx0 = ((size_t)b * NM + r0) * Uq + u;
            const size_t idx8 = idx0 + 8 * Uq;
            float2 a0 = *(const float2*)&g_alpha[idx0];
            float2 a1 = *(const float2*)&g_alpha[idx8];
            float2 o0, o1;
            o0.x = 1.0f / (1.0f + __expf(-(acc[rt][nt][0] + a0.x)));
            o0.y = 1.0f / (1.0f + __expf(-(acc[rt][nt][1] + a0.y)));
            o1.x = 1.0f / (1.0f + __expf(-(acc[rt][nt][2] + a1.x)));
            o1.y = 1.0f / (1.0f + __expf(-(acc[rt][nt][3] + a1.y)));
            *(float2*)&out[idx0] = o0;
            *(float2*)&out[idx8] = o1;
        }
    }
}

// ---------------------------------------------------------------------------
extern "C" void kernel_launch(void* const* d_in, const int* in_sizes, int n_in,
                              void* d_out, int out_size) {
    const float* seq   = (const float*)d_in[0];   // (B,N,F)
    const float* graph = (const float*)d_in[1];   // (B,N,N,M)
    const float* e_w   = (const float*)d_in[2];   // (F,U)
    const float* v_w   = (const float*)d_in[3];   // (F,M,U)
    float* out = (float*)d_out;                   // (B,N,M,U)

    cudaFuncSetAttribute(multigraph_mma_kernel,
                         cudaFuncAttributeMaxDynamicSharedMemorySize, SMEM_MAIN);

    dim3 gridA(9, 64);
    precompute_kernel<<<gridA, 256>>>(seq, e_w, v_w);

    dim3 gridT(16, 2);
    betaT_kernel<<<gridT, 256>>>();

    dim3 gridB(256, Bq);
    multigraph_mma_kernel<<<gridB, 256, SMEM_MAIN>>>(graph, out);
    (void)in_sizes; (void)n_in; (void)out_size;
}

// round 7
// speedup vs baseline: 1.1298x; 1.1298x over previous
#include <cuda_runtime.h>
#include <cuda_bf16.h>
#include <math.h>

#define Bq 2
#define Nq 2048
#define Fq 128
#define Mq 8
#define Uq 64
#define NM (Nq * Mq)            // 16384 rows of A'
#define OUTSZ (Bq * Nq * Mq * Uq)

#define JC 64                   // j per stage
#define NSTAGE (Nq / JC)        // 32

// smem per buffer: A' 128 rows x 64 j bf16 (row stride 144B) hi+lo; B 64 u x 64 j hi+lo
#define SA 144
#define AH_OFF 0
#define AL_OFF (AH_OFF + 128 * SA)      // 18432
#define BH_OFF (AL_OFF + 128 * SA)      // 36864
#define BL_OFF (BH_OFF + 64 * SA)       // 46080
#define BUF_SZ (BL_OFF + 64 * SA)       // 55296
#define SMEM_MAIN (2 * BUF_SZ)          // 110592

// device scratch (allocation-free rule)
__device__ float g_beta[Bq * Nq * Uq];
__device__ float g_alpha[OUTSZ];
__device__ unsigned short g_bTh[Bq * Uq * Nq];   // betaT hi bf16 [b][u][n]
__device__ unsigned short g_bTl[Bq * Uq * Nq];   // betaT lo bf16

__device__ __forceinline__ unsigned smem_u32(const void* p) {
    unsigned r;
    asm("{ .reg .u64 t; cvta.to.shared.u64 t, %1; cvt.u32.u64 %0, t; }"
        : "=r"(r) : "l"(p));
    return r;
}
__device__ __forceinline__ unsigned cvt_bf16x2(float lo_elem, float hi_elem) {
    unsigned r;   // low 16 bits <- lo_elem, high <- hi_elem
    asm("cvt.rn.bf16x2.f32 %0, %1, %2;" : "=r"(r) : "f"(hi_elem), "f"(lo_elem));
    return r;
}
__device__ __forceinline__ float bf_lo_f(unsigned h) { return __uint_as_float(h << 16); }
__device__ __forceinline__ float bf_hi_f(unsigned h) { return __uint_as_float(h & 0xffff0000u); }

#define LDSM4(r0, r1, r2, r3, addr) \
    asm volatile("ldmatrix.sync.aligned.m8n8.x4.shared.b16 {%0,%1,%2,%3}, [%4];" \
                 : "=r"(r0), "=r"(r1), "=r"(r2), "=r"(r3) : "r"(addr))

__device__ __forceinline__ void mma_bf16(float* c, const unsigned* a, const unsigned* b) {
    asm volatile(
        "mma.sync.aligned.m16n8k16.row.col.f32.bf16.bf16.f32 "
        "{%0,%1,%2,%3}, {%4,%5,%6,%7}, {%8,%9}, {%0,%1,%2,%3};"
        : "+f"(c[0]), "+f"(c[1]), "+f"(c[2]), "+f"(c[3])
        : "r"(a[0]), "r"(a[1]), "r"(a[2]), "r"(a[3]), "r"(b[0]), "r"(b[1]));
}

// ---------------------------------------------------------------------------
// Kernel A: beta = seq @ e_w, alpha = seq @ v_w. (unchanged, works)
// ---------------------------------------------------------------------------
__global__ void __launch_bounds__(256) precompute_kernel(
        const float* __restrict__ seq,
        const float* __restrict__ e_w,
        const float* __restrict__ v_w) {
    __shared__ float sS[64][33];
    __shared__ float sW[32][68];

    const int bx = blockIdx.x;
    const int by = blockIdx.y;
    const int row0 = by * 64;

    const float* wsrc;
    int wstride, c0;
    if (bx == 0) { wsrc = e_w; wstride = Uq;      c0 = 0; }
    else         { wsrc = v_w; wstride = Mq * Uq; c0 = (bx - 1) * 64; }

    const int tid = threadIdx.x;
    const int tx = tid & 15;
    const int ty = tid >> 4;

    float acc[4][4];
#pragma unroll
    for (int r = 0; r < 4; r++)
#pragma unroll
        for (int c = 0; c < 4; c++) acc[r][c] = 0.f;

    for (int fb = 0; fb < Fq; fb += 32) {
#pragma unroll
        for (int k = 0; k < 2; k++) {
            int v = tid + k * 256;
            int r = v >> 3, fq = (v & 7) * 4;
            float4 t = *(const float4*)&seq[(row0 + r) * Fq + fb + fq];
            sS[r][fq + 0] = t.x; sS[r][fq + 1] = t.y;
            sS[r][fq + 2] = t.z; sS[r][fq + 3] = t.w;
        }
#pragma unroll
        for (int k = 0; k < 2; k++) {
            int v = tid + k * 256;
            int f = v >> 4, cq = (v & 15) * 4;
            float4 t = *(const float4*)&wsrc[(fb + f) * wstride + c0 + cq];
            *(float4*)&sW[f][cq] = t;
        }
        __syncthreads();

#pragma unroll 4
        for (int f = 0; f < 32; f++) {
            float a[4];
#pragma unroll
            for (int r = 0; r < 4; r++) a[r] = sS[ty * 4 + r][f];
            float4 b4 = *(const float4*)&sW[f][tx * 4];
            float bb[4] = {b4.x, b4.y, b4.z, b4.w};
#pragma unroll
            for (int r = 0; r < 4; r++)
#pragma unroll
                for (int c = 0; c < 4; c++)
                    acc[r][c] = fmaf(a[r], bb[c], acc[r][c]);
        }
        __syncthreads();
    }

#pragma unroll
    for (int r = 0; r < 4; r++) {
        const int bn = row0 + ty * 4 + r;
#pragma unroll
        for (int c = 0; c < 4; c++) {
            const int col = tx * 4 + c;
            if (bx == 0) g_beta[bn * Uq + col] = acc[r][c];
            else         g_alpha[bn * (Mq * Uq) + c0 + col] = acc[r][c];
        }
    }
}

// ---------------------------------------------------------------------------
// Kernel T: betaT hi/lo bf16 (unchanged, works)
// ---------------------------------------------------------------------------
__global__ void __launch_bounds__(256) betaT_kernel() {
    __shared__ float s[128][65];
    const int b  = blockIdx.y;
    const int n0 = blockIdx.x * 128;
    const int tid = threadIdx.x;

#pragma unroll
    for (int k = 0; k < 8; k++) {
        int v = tid + k * 256;
        int n = v >> 4, uq = (v & 15) * 4;
        float4 t = *(const float4*)&g_beta[((b * Nq) + n0 + n) * Uq + uq];
        s[n][uq + 0] = t.x; s[n][uq + 1] = t.y;
        s[n][uq + 2] = t.z; s[n][uq + 3] = t.w;
    }
    __syncthreads();

    const int w = tid >> 5, l = tid & 31;
#pragma unroll
    for (int r = 0; r < 8; r++) {
        int u = w * 8 + r;
        float a0 = s[4 * l + 0][u], a1 = s[4 * l + 1][u];
        float a2 = s[4 * l + 2][u], a3 = s[4 * l + 3][u];
        unsigned h01 = cvt_bf16x2(a0, a1), h23 = cvt_bf16x2(a2, a3);
        float r0 = a0 - bf_lo_f(h01), r1 = a1 - bf_hi_f(h01);
        float r2 = a2 - bf_lo_f(h23), r3 = a3 - bf_hi_f(h23);
        unsigned l01 = cvt_bf16x2(r0, r1), l23 = cvt_bf16x2(r2, r3);
        size_t idx = (size_t)(b * Uq + u) * Nq + n0 + 4 * l;
        *(uint2*)&g_bTh[idx] = make_uint2(h01, h23);
        *(uint2*)&g_bTl[idx] = make_uint2(l01, l23);
    }
}

// ---------------------------------------------------------------------------
// Kernel B (main): fused, double-buffered, 3-pass bf16 mma.
// CTA tile: 128 A'-rows (16 i x 8 m) x 64 u x 64 j per stage. 256 threads.
// Warps 4x2: wr = w>>1 (32 rows), wc = w&1 (32 u). Warp tile 32 x 32.
// A staged with COALESCED float4 LDG + shfl.bfly(2) j-pairing + conflict-free
// STS.32 (SA=144 tiles all 32 banks). One __syncthreads per stage.
// ---------------------------------------------------------------------------
__global__ void __launch_bounds__(256, 2) multigraph_mma_kernel(
        const float* __restrict__ graph,
        float* __restrict__ out) {
    extern __shared__ __align__(16) char smem[];
    const unsigned sb = smem_u32(smem);

    const int tid = threadIdx.x;
    const int l = tid & 31;
    const int w = tid >> 5;
    const int wr = w >> 1;                   // 0..3
    const int wc = w & 1;                    // 0..1

    const int rt0 = blockIdx.x * 128;        // global A' row base
    const int b   = blockIdx.y;
    const int i0  = rt0 >> 3;                // graph i base (16 i per block)

    // A staging constants: lane covers (j = jj, m-half mh) of rows il*8..
    const int rem = tid & 127;
    const int jj  = rem >> 1;                // 0..63
    const int mh  = rem & 1;
    const int odd = jj & 1;
    const int ilb = tid >> 7;                // 0 or 1
    const int jec = (jj & ~1) * 2;           // byte col of even-j word
    // B staging
    const int bu  = tid >> 3;                // 0..31
    const int bjq = tid & 7;

    float acc[2][4][4];
#pragma unroll
    for (int rt = 0; rt < 2; rt++)
#pragma unroll
        for (int nt = 0; nt < 4; nt++)
#pragma unroll
            for (int k = 0; k < 4; k++) acc[rt][nt][k] = 0.f;

    // ldmatrix lane addressing (proven mapping, retiled)
    const unsigned aRow = (unsigned)(wr * 32 + (l & 15)) * SA + ((l >> 4) * 16);
    const unsigned bRow = (unsigned)(wc * 32 + (l & 7) + ((l >> 4) & 1) * 8) * SA
                        + (((l >> 3) & 1) * 16);

    const size_t gbase = ((size_t)b * Nq + i0) * Nq * Mq;
    const size_t bTb = (size_t)b * Uq * Nq;

    float4 av[4];
    uint4 bhv[2], blv[2];

    // ---- coalesced A LDG: half h covers il = (h*4+c)*2 + ilb
    auto ldgA = [&](int s, int h) {
        const int j0 = s * JC;
#pragma unroll
        for (int c = 0; c < 4; c++) {
            int il = (h * 4 + c) * 2 + ilb;
            av[c] = *(const float4*)(graph + gbase
                        + ((size_t)il * Nq + j0 + jj) * Mq + mh * 4);
        }
    };
    // ---- shuffle j-pair + cvt + STS.32 into buffer p
    auto stsA = [&](int p, int h) {
        char* buf = smem + p * BUF_SZ;
#pragma unroll
        for (int c = 0; c < 4; c++) {
            int il = (h * 4 + c) * 2 + ilb;
            float4 own = av[c];
            float4 rcv;
            rcv.x = __shfl_xor_sync(0xffffffffu, own.x, 2);
            rcv.y = __shfl_xor_sync(0xffffffffu, own.y, 2);
            rcv.z = __shfl_xor_sync(0xffffffffu, own.z, 2);
            rcv.w = __shfl_xor_sync(0xffffffffu, own.w, 2);
            const float* pje = odd ? (const float*)&rcv : (const float*)&own;
            const float* pjo = odd ? (const float*)&own : (const float*)&rcv;
#pragma unroll
            for (int k = 0; k < 2; k++) {
                int q = odd * 2 + k;               // m index within quad
                unsigned row = (unsigned)(il * 8 + mh * 4 + q);
                unsigned h2 = cvt_bf16x2(pje[q], pjo[q]);
                float r0 = pje[q] - bf_lo_f(h2);
                float r1 = pjo[q] - bf_hi_f(h2);
                unsigned lo = cvt_bf16x2(r0, r1);
                *(unsigned*)(buf + AH_OFF + row * SA + jec) = h2;
                *(unsigned*)(buf + AL_OFF + row * SA + jec) = lo;
            }
        }
    };
    auto ldgB = [&](int s) {
        const int j0 = s * JC;
        size_t src = bTb + (size_t)bu * Nq + j0 + bjq * 8;
        bhv[0] = *(const uint4*)&g_bTh[src];
        blv[0] = *(const uint4*)&g_bTl[src];
        src += (size_t)32 * Nq;
        bhv[1] = *(const uint4*)&g_bTh[src];
        blv[1] = *(const uint4*)&g_bTl[src];
    };
    auto stsB = [&](int p) {
        char* buf = smem + p * BUF_SZ;
#pragma unroll
        for (int k = 0; k < 2; k++) {
            unsigned off = (unsigned)(bu + k * 32) * SA + bjq * 16;
            *(uint4*)(buf + BH_OFF + off) = bhv[k];
            *(uint4*)(buf + BL_OFF + off) = blv[k];
        }
    };
    // ---- mma over 2 k16-steps of buffer p
    auto mmaHalf = [&](int p, int ks0) {
        const unsigned base = sb + (unsigned)p * BUF_SZ;
#pragma unroll
        for (int ks = ks0; ks < ks0 + 2; ks++) {
            unsigned ah[2][4], al[2][4], bh[8], bl[8];
#pragma unroll
            for (int rt = 0; rt < 2; rt++) {
                unsigned aoff = aRow + (unsigned)rt * 16 * SA + ks * 32;
                LDSM4(ah[rt][0], ah[rt][1], ah[rt][2], ah[rt][3], base + AH_OFF + aoff);
                LDSM4(al[rt][0], al[rt][1], al[rt][2], al[rt][3], base + AL_OFF + aoff);
            }
#pragma unroll
            for (int g = 0; g < 2; g++) {
                unsigned boff = bRow + (unsigned)g * 16 * SA + ks * 32;
                LDSM4(bh[g*4+0], bh[g*4+1], bh[g*4+2], bh[g*4+3], base + BH_OFF + boff);
                LDSM4(bl[g*4+0], bl[g*4+1], bl[g*4+2], bl[g*4+3], base + BL_OFF + boff);
            }
#pragma unroll
            for (int rt = 0; rt < 2; rt++)
#pragma unroll
                for (int nt = 0; nt < 4; nt++) {
                    mma_bf16(acc[rt][nt], ah[rt], &bh[nt * 2]);
                    mma_bf16(acc[rt][nt], al[rt], &bh[nt * 2]);
                    mma_bf16(acc[rt][nt], ah[rt], &bl[nt * 2]);
                }
        }
    };

    // prologue: stage 0 into buffer 0
    ldgB(0);
    ldgA(0, 0); stsA(0, 0);
    ldgA(0, 1); stsA(0, 1);
    stsB(0);

#pragma unroll 1
    for (int s = 0; s < NSTAGE; s++) {
        __syncthreads();                     // buf[s&1] ready; buf[s&1^1] free
        const int p = s & 1, pn = p ^ 1;
        if (s + 1 < NSTAGE) { ldgB(s + 1); ldgA(s + 1, 0); }
        mmaHalf(p, 0);
        if (s + 1 < NSTAGE) { stsA(pn, 0); ldgA(s + 1, 1); }
        mmaHalf(p, 2);
        if (s + 1 < NSTAGE) { stsA(pn, 1); stsB(pn); }
    }

    // fused epilogue: + alpha, sigmoid, store
#pragma unroll
    for (int rt = 0; rt < 2; rt++) {
        const int r0 = rt0 + wr * 32 + rt * 16 + (l >> 2);
#pragma unroll
        for (int nt = 0; nt < 4; nt++) {
            const int u = wc * 32 + nt * 8 + (l & 3) * 2;
            const size_t idx0 = ((size_t)b * NM + r0) * Uq + u;
            const size_t idx8 = idx0 + 8 * Uq;
            float2 a0 = *(const float2*)&g_alpha[idx0];
            float2 a1 = *(const float2*)&g_alpha[idx8];
            float2 o0, o1;
            o0.x = 1.0f / (1.0f + __expf(-(acc[rt][nt][0] + a0.x)));
            o0.y = 1.0f / (1.0f + __expf(-(acc[rt][nt][1] + a0.y)));
            o1.x = 1.0f / (1.0f + __expf(-(acc[rt][nt][2] + a1.x)));
            o1.y = 1.0f / (1.0f + __expf(-(acc[rt][nt][3] + a1.y)));
            *(float2*)&out[idx0] = o0;
            *(float2*)&out[idx8] = o1;
        }
    }
}

// ---------------------------------------------------------------------------
extern "C" void kernel_launch(void* const* d_in, const int* in_sizes, int n_in,
                              void* d_out, int out_size) {
    const float* seq   = (const float*)d_in[0];   // (B,N,F)
    const float* graph = (const float*)d_in[1];   // (B,N,N,M)
    const float* e_w   = (const float*)d_in[2];   // (F,U)
    const float* v_w   = (const float*)d_in[3];   // (F,M,U)
    float* out = (float*)d_out;                   // (B,N,M,U)

    cudaFuncSetAttribute(multigraph_mma_kernel,
                         cudaFuncAttributeMaxDynamicSharedMemorySize, SMEM_MAIN);

    dim3 gridA(9, 64);
    precompute_kernel<<<gridA, 256>>>(seq, e_w, v_w);

    dim3 gridT(16, 2);
    betaT_kernel<<<gridT, 256>>>();

    dim3 gridB(128, Bq);
    multigraph_mma_kernel<<<gridB, 256, SMEM_MAIN>>>(graph, out);
    (void)in_sizes; (void)n_in; (void)out_size;
}

// round 9
// speedup vs baseline: 1.2407x; 1.0981x over previous
#include <cuda_runtime.h>
#include <cuda_bf16.h>
#include <math.h>

#define Bq 2
#define Nq 2048
#define Fq 128
#define Mq 8
#define Uq 64
#define NM (Nq * Mq)            // 16384 rows of A'
#define OUTSZ (Bq * Nq * Mq * Uq)
#define WCOLS 576               // 64 (e_w) + 512 (v_w)

#define JC 64                   // j per stage (main)
#define NSTAGE (Nq / JC)        // 32

// ---- main kernel smem (unchanged from R7)
#define SA 144
#define AH_OFF 0
#define AL_OFF (AH_OFF + 128 * SA)
#define BH_OFF (AL_OFF + 128 * SA)
#define BL_OFF (BH_OFF + 64 * SA)
#define BUF_SZ (BL_OFF + 64 * SA)
#define SMEM_MAIN (2 * BUF_SZ)          // 110592

// ---- precompute-mma smem
#define SA2 272
#define P_AH 0
#define P_AL (P_AH + 128 * SA2)
#define P_WH (P_AL + 128 * SA2)
#define P_WL (P_WH + 64 * SA2)
#define SMEM_PRE (P_WL + 64 * SA2)      // 104448
#define CS 66                            // fp32 C-bounce stride (words)

// device scratch (allocation-free rule)
__device__ float g_alpha[OUTSZ];
__device__ unsigned short g_bTh[Bq * Uq * Nq];   // betaT hi bf16 [b][u][n]
__device__ unsigned short g_bTl[Bq * Uq * Nq];   // betaT lo bf16
__device__ unsigned short g_wTh[WCOLS * Fq];     // W^T hi bf16 [col][f]
__device__ unsigned short g_wTl[WCOLS * Fq];     // W^T lo bf16

__device__ __forceinline__ unsigned smem_u32(const void* p) {
    unsigned r;
    asm("{ .reg .u64 t; cvta.to.shared.u64 t, %1; cvt.u32.u64 %0, t; }"
        : "=r"(r) : "l"(p));
    return r;
}
__device__ __forceinline__ unsigned cvt_bf16x2(float lo_elem, float hi_elem) {
    unsigned r;   // low 16 bits <- lo_elem, high <- hi_elem
    asm("cvt.rn.bf16x2.f32 %0, %1, %2;" : "=r"(r) : "f"(hi_elem), "f"(lo_elem));
    return r;
}
__device__ __forceinline__ float bf_lo_f(unsigned h) { return __uint_as_float(h << 16); }
__device__ __forceinline__ float bf_hi_f(unsigned h) { return __uint_as_float(h & 0xffff0000u); }

#define LDSM4(r0, r1, r2, r3, addr) \
    asm volatile("ldmatrix.sync.aligned.m8n8.x4.shared.b16 {%0,%1,%2,%3}, [%4];" \
                 : "=r"(r0), "=r"(r1), "=r"(r2), "=r"(r3) : "r"(addr))

__device__ __forceinline__ void mma_bf16(float* c, const unsigned* a, const unsigned* b) {
    asm volatile(
        "mma.sync.aligned.m16n8k16.row.col.f32.bf16.bf16.f32 "
        "{%0,%1,%2,%3}, {%4,%5,%6,%7}, {%8,%9}, {%0,%1,%2,%3};"
        : "+f"(c[0]), "+f"(c[1]), "+f"(c[2]), "+f"(c[3])
        : "r"(a[0]), "r"(a[1]), "r"(a[2]), "r"(a[3]), "r"(b[0]), "r"(b[1]));
}

// ---------------------------------------------------------------------------
// Kernel W: transpose+split weights -> g_wT[col][f] bf16 hi/lo.
// Grid 9 x 256. bx=0: e_w -> store cols 0..63. bx>0: v_w cols (bx-1)*64
// -> store cols bx*64 .. bx*64+63.  (FIXED: full tile staged; no collision.)
// ---------------------------------------------------------------------------
__global__ void __launch_bounds__(256) wprep_kernel(
        const float* __restrict__ e_w, const float* __restrict__ v_w) {
    __shared__ float s[128][69];
    const int bx = blockIdx.x;
    const float* wsrc;
    int wstride, c0;
    if (bx == 0) { wsrc = e_w; wstride = Uq;      c0 = 0; }
    else         { wsrc = v_w; wstride = Mq * Uq; c0 = (bx - 1) * 64; }
    const int sc0 = bx * 64;             // store base in g_wT
    const int tid = threadIdx.x;

    // stage FULL 128 f x 64 col tile: 2048 float4
#pragma unroll
    for (int it = 0; it < 8; it++) {
        int v = tid + it * 256;          // < 2048
        int f = v >> 4, cq = (v & 15) * 4;
        float4 t = *(const float4*)&wsrc[f * wstride + c0 + cq];
        s[f][cq + 0] = t.x; s[f][cq + 1] = t.y;
        s[f][cq + 2] = t.z; s[f][cq + 3] = t.w;
    }
    __syncthreads();

    const int c = tid >> 2;              // 0..63
    const int fq8 = tid & 3;
#pragma unroll
    for (int it = 0; it < 4; it++) {
        int f0 = (fq8 + it * 4) * 8;     // 0..120 step 8
        unsigned h[4], lo[4];
#pragma unroll
        for (int k = 0; k < 4; k++) {
            float a0 = s[f0 + 2 * k][c], a1 = s[f0 + 2 * k + 1][c];
            h[k] = cvt_bf16x2(a0, a1);
            float r0 = a0 - bf_lo_f(h[k]);
            float r1 = a1 - bf_hi_f(h[k]);
            lo[k] = cvt_bf16x2(r0, r1);
        }
        size_t idx = (size_t)(sc0 + c) * Fq + f0;
        *(uint4*)&g_wTh[idx] = make_uint4(h[0], h[1], h[2], h[3]);
        *(uint4*)&g_wTl[idx] = make_uint4(lo[0], lo[1], lo[2], lo[3]);
    }
}

// ---------------------------------------------------------------------------
// Kernel P: beta|alpha = seq @ [e_w | v_w] via bf16 3-pass mma. K=128, 1 stage.
// Grid (9, 32) x 256 thr. bx=0 -> beta (writes g_bT transposed bf16 hi/lo),
// bx>0 -> alpha cols (bx-1)*64 (writes g_alpha fp32).
// ---------------------------------------------------------------------------
__global__ void __launch_bounds__(256, 2) precompute_mma_kernel(
        const float* __restrict__ seq) {
    extern __shared__ __align__(16) char ps[];
    const unsigned sb = smem_u32(ps);

    const int tid = threadIdx.x;
    const int l = tid & 31;
    const int w = tid >> 5;
    const int wr = w >> 1;
    const int wc = w & 1;

    const int bx = blockIdx.x;
    const int by = blockIdx.y;
    const int n0 = by * 128;             // global seq row base

    // ---- stage A: seq 128 rows x 128 f, hi/lo bf16 (f-pairs within float4)
#pragma unroll
    for (int it = 0; it < 16; it++) {
        int v = tid + it * 256;          // < 4096
        int r = v >> 5, fq = v & 31;
        float4 t = *(const float4*)&seq[(size_t)(n0 + r) * Fq + fq * 4];
        unsigned h0 = cvt_bf16x2(t.x, t.y), h1 = cvt_bf16x2(t.z, t.w);
        unsigned l0 = cvt_bf16x2(t.x - bf_lo_f(h0), t.y - bf_hi_f(h0));
        unsigned l1 = cvt_bf16x2(t.z - bf_lo_f(h1), t.w - bf_hi_f(h1));
        unsigned off = (unsigned)r * SA2 + fq * 8;
        *(uint2*)(ps + P_AH + off) = make_uint2(h0, h1);
        *(uint2*)(ps + P_AL + off) = make_uint2(l0, l1);
    }
    // ---- stage W: 64 cols x 128 f from pre-split g_wT (direct copies)
    {
        const int c0 = bx * 64;          // col base in g_wT
#pragma unroll
        for (int it = 0; it < 4; it++) {
            int v = tid + it * 256;      // < 1024
            int c = v >> 4, fo = (v & 15);
            size_t src = (size_t)(c0 + c) * Fq + fo * 8;
            unsigned off = (unsigned)c * SA2 + fo * 16;
            *(uint4*)(ps + P_WH + off) = *(const uint4*)&g_wTh[src];
            *(uint4*)(ps + P_WL + off) = *(const uint4*)&g_wTl[src];
        }
    }
    __syncthreads();

    float acc[2][4][4];
#pragma unroll
    for (int rt = 0; rt < 2; rt++)
#pragma unroll
        for (int nt = 0; nt < 4; nt++)
#pragma unroll
            for (int k = 0; k < 4; k++) acc[rt][nt][k] = 0.f;

    const unsigned aRow = (unsigned)(wr * 32 + (l & 15)) * SA2 + ((l >> 4) * 16);
    const unsigned bRow = (unsigned)(wc * 32 + (l & 7) + ((l >> 4) & 1) * 8) * SA2
                        + (((l >> 3) & 1) * 16);

#pragma unroll
    for (int ks = 0; ks < 8; ks++) {
        unsigned ah[2][4], al[2][4], bh[8], bl[8];
#pragma unroll
        for (int rt = 0; rt < 2; rt++) {
            unsigned aoff = aRow + (unsigned)rt * 16 * SA2 + ks * 32;
            LDSM4(ah[rt][0], ah[rt][1], ah[rt][2], ah[rt][3], sb + P_AH + aoff);
            LDSM4(al[rt][0], al[rt][1], al[rt][2], al[rt][3], sb + P_AL + aoff);
        }
#pragma unroll
        for (int g = 0; g < 2; g++) {
            unsigned boff = bRow + (unsigned)g * 16 * SA2 + ks * 32;
            LDSM4(bh[g*4+0], bh[g*4+1], bh[g*4+2], bh[g*4+3], sb + P_WH + boff);
            LDSM4(bl[g*4+0], bl[g*4+1], bl[g*4+2], bl[g*4+3], sb + P_WL + boff);
        }
#pragma unroll
        for (int rt = 0; rt < 2; rt++)
#pragma unroll
            for (int nt = 0; nt < 4; nt++) {
                mma_bf16(acc[rt][nt], ah[rt], &bh[nt * 2]);
                mma_bf16(acc[rt][nt], al[rt], &bh[nt * 2]);
                mma_bf16(acc[rt][nt], ah[rt], &bl[nt * 2]);
            }
    }

    if (bx > 0) {
        // alpha: write fp32, cols (bx-1)*64 of the 512 (m,u) columns
        const int c0 = (bx - 1) * 64;
#pragma unroll
        for (int rt = 0; rt < 2; rt++) {
            const int r0 = n0 + wr * 32 + rt * 16 + (l >> 2);
#pragma unroll
            for (int nt = 0; nt < 4; nt++) {
                const int cu = c0 + wc * 32 + nt * 8 + (l & 3) * 2;
                const size_t idx0 = (size_t)r0 * (Mq * Uq) + cu;
                const size_t idx8 = idx0 + 8 * (Mq * Uq);
                *(float2*)&g_alpha[idx0] = make_float2(acc[rt][nt][0], acc[rt][nt][1]);
                *(float2*)&g_alpha[idx8] = make_float2(acc[rt][nt][2], acc[rt][nt][3]);
            }
        }
    } else {
        // beta: bounce C through smem, emit transposed bf16 hi/lo [b][u][n]
        __syncthreads();                 // smem A/W no longer needed
        float* cs = (float*)ps;          // [128][CS]
#pragma unroll
        for (int rt = 0; rt < 2; rt++) {
            const int r0 = wr * 32 + rt * 16 + (l >> 2);
#pragma unroll
            for (int nt = 0; nt < 4; nt++) {
                const int u = wc * 32 + nt * 8 + (l & 3) * 2;
                *(float2*)&cs[r0 * CS + u] = make_float2(acc[rt][nt][0], acc[rt][nt][1]);
                *(float2*)&cs[(r0 + 8) * CS + u] = make_float2(acc[rt][nt][2], acc[rt][nt][3]);
            }
        }
        __syncthreads();
        const int b   = n0 >> 11;
        const int nin = n0 & 2047;
        const int u  = tid >> 2;         // 0..63
        const int nq = tid & 3;
#pragma unroll
        for (int it = 0; it < 8; it++) {
            int n = nq * 4 + it * 16;
            float v0 = cs[(n + 0) * CS + u], v1 = cs[(n + 1) * CS + u];
            float v2 = cs[(n + 2) * CS + u], v3 = cs[(n + 3) * CS + u];
            unsigned h01 = cvt_bf16x2(v0, v1), h23 = cvt_bf16x2(v2, v3);
            unsigned l01 = cvt_bf16x2(v0 - bf_lo_f(h01), v1 - bf_hi_f(h01));
            unsigned l23 = cvt_bf16x2(v2 - bf_lo_f(h23), v3 - bf_hi_f(h23));
            size_t idx = (size_t)(b * Uq + u) * Nq + nin + n;
            *(uint2*)&g_bTh[idx] = make_uint2(h01, h23);
            *(uint2*)&g_bTl[idx] = make_uint2(l01, l23);
        }
    }
}

// ---------------------------------------------------------------------------
// Kernel B (main): UNCHANGED from round 7 (fused, double-buffered, 3-pass).
// ---------------------------------------------------------------------------
__global__ void __launch_bounds__(256, 2) multigraph_mma_kernel(
        const float* __restrict__ graph,
        float* __restrict__ out) {
    extern __shared__ __align__(16) char smem[];
    const unsigned sb = smem_u32(smem);

    const int tid = threadIdx.x;
    const int l = tid & 31;
    const int w = tid >> 5;
    const int wr = w >> 1;
    const int wc = w & 1;

    const int rt0 = blockIdx.x * 128;
    const int b   = blockIdx.y;
    const int i0  = rt0 >> 3;

    const int rem = tid & 127;
    const int jj  = rem >> 1;
    const int mh  = rem & 1;
    const int odd = jj & 1;
    const int ilb = tid >> 7;
    const int jec = (jj & ~1) * 2;
    const int bu  = tid >> 3;
    const int bjq = tid & 7;

    float acc[2][4][4];
#pragma unroll
    for (int rt = 0; rt < 2; rt++)
#pragma unroll
        for (int nt = 0; nt < 4; nt++)
#pragma unroll
            for (int k = 0; k < 4; k++) acc[rt][nt][k] = 0.f;

    const unsigned aRow = (unsigned)(wr * 32 + (l & 15)) * SA + ((l >> 4) * 16);
    const unsigned bRow = (unsigned)(wc * 32 + (l & 7) + ((l >> 4) & 1) * 8) * SA
                        + (((l >> 3) & 1) * 16);

    const size_t gbase = ((size_t)b * Nq + i0) * Nq * Mq;
    const size_t bTb = (size_t)b * Uq * Nq;

    float4 av[4];
    uint4 bhv[2], blv[2];

    auto ldgA = [&](int s, int h) {
        const int j0 = s * JC;
#pragma unroll
        for (int c = 0; c < 4; c++) {
            int il = (h * 4 + c) * 2 + ilb;
            av[c] = *(const float4*)(graph + gbase
                        + ((size_t)il * Nq + j0 + jj) * Mq + mh * 4);
        }
    };
    auto stsA = [&](int p, int h) {
        char* buf = smem + p * BUF_SZ;
#pragma unroll
        for (int c = 0; c < 4; c++) {
            int il = (h * 4 + c) * 2 + ilb;
            float4 own = av[c];
            float4 rcv;
            rcv.x = __shfl_xor_sync(0xffffffffu, own.x, 2);
            rcv.y = __shfl_xor_sync(0xffffffffu, own.y, 2);
            rcv.z = __shfl_xor_sync(0xffffffffu, own.z, 2);
            rcv.w = __shfl_xor_sync(0xffffffffu, own.w, 2);
            const float* pje = odd ? (const float*)&rcv : (const float*)&own;
            const float* pjo = odd ? (const float*)&own : (const float*)&rcv;
#pragma unroll
            for (int k = 0; k < 2; k++) {
                int q = odd * 2 + k;
                unsigned row = (unsigned)(il * 8 + mh * 4 + q);
                unsigned h2 = cvt_bf16x2(pje[q], pjo[q]);
                float r0 = pje[q] - bf_lo_f(h2);
                float r1 = pjo[q] - bf_hi_f(h2);
                unsigned lo = cvt_bf16x2(r0, r1);
                *(unsigned*)(buf + AH_OFF + row * SA + jec) = h2;
                *(unsigned*)(buf + AL_OFF + row * SA + jec) = lo;
            }
        }
    };
    auto ldgB = [&](int s) {
        const int j0 = s * JC;
        size_t src = bTb + (size_t)bu * Nq + j0 + bjq * 8;
        bhv[0] = *(const uint4*)&g_bTh[src];
        blv[0] = *(const uint4*)&g_bTl[src];
        src += (size_t)32 * Nq;
        bhv[1] = *(const uint4*)&g_bTh[src];
        blv[1] = *(const uint4*)&g_bTl[src];
    };
    auto stsB = [&](int p) {
        char* buf = smem + p * BUF_SZ;
#pragma unroll
        for (int k = 0; k < 2; k++) {
            unsigned off = (unsigned)(bu + k * 32) * SA + bjq * 16;
            *(uint4*)(buf + BH_OFF + off) = bhv[k];
            *(uint4*)(buf + BL_OFF + off) = blv[k];
        }
    };
    auto mmaHalf = [&](int p, int ks0) {
        const unsigned base = sb + (unsigned)p * BUF_SZ;
#pragma unroll
        for (int ks = ks0; ks < ks0 + 2; ks++) {
            unsigned ah[2][4], al[2][4], bh[8], bl[8];
#pragma unroll
            for (int rt = 0; rt < 2; rt++) {
                unsigned aoff = aRow + (unsigned)rt * 16 * SA + ks * 32;
                LDSM4(ah[rt][0], ah[rt][1], ah[rt][2], ah[rt][3], base + AH_OFF + aoff);
                LDSM4(al[rt][0], al[rt][1], al[rt][2], al[rt][3], base + AL_OFF + aoff);
            }
#pragma unroll
            for (int g = 0; g < 2; g++) {
                unsigned boff = bRow + (unsigned)g * 16 * SA + ks * 32;
                LDSM4(bh[g*4+0], bh[g*4+1], bh[g*4+2], bh[g*4+3], base + BH_OFF + boff);
                LDSM4(bl[g*4+0], bl[g*4+1], bl[g*4+2], bl[g*4+3], base + BL_OFF + boff);
            }
#pragma unroll
            for (int rt = 0; rt < 2; rt++)
#pragma unroll
                for (int nt = 0; nt < 4; nt++) {
                    mma_bf16(acc[rt][nt], ah[rt], &bh[nt * 2]);
                    mma_bf16(acc[rt][nt], al[rt], &bh[nt * 2]);
                    mma_bf16(acc[rt][nt], ah[rt], &bl[nt * 2]);
                }
        }
    };

    ldgB(0);
    ldgA(0, 0); stsA(0, 0);
    ldgA(0, 1); stsA(0, 1);
    stsB(0);

#pragma unroll 1
    for (int s = 0; s < NSTAGE; s++) {
        __syncthreads();
        const int p = s & 1, pn = p ^ 1;
        if (s + 1 < NSTAGE) { ldgB(s + 1); ldgA(s + 1, 0); }
        mmaHalf(p, 0);
        if (s + 1 < NSTAGE) { stsA(pn, 0); ldgA(s + 1, 1); }
        mmaHalf(p, 2);
        if (s + 1 < NSTAGE) { stsA(pn, 1); stsB(pn); }
    }

#pragma unroll
    for (int rt = 0; rt < 2; rt++) {
        const int r0 = rt0 + wr * 32 + rt * 16 + (l >> 2);
#pragma unroll
        for (int nt = 0; nt < 4; nt++) {
            const int u = wc * 32 + nt * 8 + (l & 3) * 2;
            const size_t idx0 = ((size_t)b * NM + r0) * Uq + u;
            const size_t idx8 = idx0 + 8 * Uq;
            float2 a0 = *(const float2*)&g_alpha[idx0];
            float2 a1 = *(const float2*)&g_alpha[idx8];
            float2 o0, o1;
            o0.x = 1.0f / (1.0f + __expf(-(acc[rt][nt][0] + a0.x)));
            o0.y = 1.0f / (1.0f + __expf(-(acc[rt][nt][1] + a0.y)));
            o1.x = 1.0f / (1.0f + __expf(-(acc[rt][nt][2] + a1.x)));
            o1.y = 1.0f / (1.0f + __expf(-(acc[rt][nt][3] + a1.y)));
            *(float2*)&out[idx0] = o0;
            *(float2*)&out[idx8] = o1;
        }
    }
}

// ---------------------------------------------------------------------------
extern "C" void kernel_launch(void* const* d_in, const int* in_sizes, int n_in,
                              void* d_out, int out_size) {
    const float* seq   = (const float*)d_in[0];   // (B,N,F)
    const float* graph = (const float*)d_in[1];   // (B,N,N,M)
    const float* e_w   = (const float*)d_in[2];   // (F,U)
    const float* v_w   = (const float*)d_in[3];   // (F,M,U)
    float* out = (float*)d_out;                   // (B,N,M,U)

    cudaFuncSetAttribute(precompute_mma_kernel,
                         cudaFuncAttributeMaxDynamicSharedMemorySize, SMEM_PRE);
    cudaFuncSetAttribute(multigraph_mma_kernel,
                         cudaFuncAttributeMaxDynamicSharedMemorySize, SMEM_MAIN);

    wprep_kernel<<<9, 256>>>(e_w, v_w);

    dim3 gridP(9, 32);
    precompute_mma_kernel<<<gridP, 256, SMEM_PRE>>>(seq);

    dim3 gridB(128, Bq);
    multigraph_mma_kernel<<<gridB, 256, SMEM_MAIN>>>(graph, out);
    (void)in_sizes; (void)n_in; (void)out_size;
}

// round 10
// speedup vs baseline: 1.2626x; 1.0176x over previous
#include <cuda_runtime.h>
#include <cuda_bf16.h>
#include <math.h>

#define Bq 2
#define Nq 2048
#define Fq 128
#define Mq 8
#define Uq 64
#define NM (Nq * Mq)            // 16384 rows of A'
#define OUTSZ (Bq * Nq * Mq * Uq)

#define JC 64                   // j per stage (main)
#define NSTAGE (Nq / JC)        // 32

// ---- main kernel smem (unchanged from R7/R9)
#define SA 144
#define AH_OFF 0
#define AL_OFF (AH_OFF + 128 * SA)
#define BH_OFF (AL_OFF + 128 * SA)
#define BL_OFF (BH_OFF + 64 * SA)
#define BUF_SZ (BL_OFF + 64 * SA)
#define SMEM_MAIN (2 * BUF_SZ)          // 110592

// ---- precompute-mma smem
#define SA2 272
#define P_AH 0
#define P_AL (P_AH + 128 * SA2)
#define P_WH (P_AL + 128 * SA2)
#define P_WL (P_WH + 64 * SA2)
#define SMEM_PRE (P_WL + 64 * SA2)      // 104448
#define CS 66                            // fp32 C-bounce stride (words)
#define WS 69                            // fp32 W-bounce stride (words)

// device scratch (allocation-free rule)
__device__ float g_alpha[OUTSZ];
__device__ unsigned short g_bTh[Bq * Uq * Nq];   // betaT hi bf16 [b][u][n]
__device__ unsigned short g_bTl[Bq * Uq * Nq];   // betaT lo bf16

__device__ __forceinline__ unsigned smem_u32(const void* p) {
    unsigned r;
    asm("{ .reg .u64 t; cvta.to.shared.u64 t, %1; cvt.u32.u64 %0, t; }"
        : "=r"(r) : "l"(p));
    return r;
}
__device__ __forceinline__ unsigned cvt_bf16x2(float lo_elem, float hi_elem) {
    unsigned r;   // low 16 bits <- lo_elem, high <- hi_elem
    asm("cvt.rn.bf16x2.f32 %0, %1, %2;" : "=r"(r) : "f"(hi_elem), "f"(lo_elem));
    return r;
}
__device__ __forceinline__ float bf_lo_f(unsigned h) { return __uint_as_float(h << 16); }
__device__ __forceinline__ float bf_hi_f(unsigned h) { return __uint_as_float(h & 0xffff0000u); }

#define LDSM4(r0, r1, r2, r3, addr) \
    asm volatile("ldmatrix.sync.aligned.m8n8.x4.shared.b16 {%0,%1,%2,%3}, [%4];" \
                 : "=r"(r0), "=r"(r1), "=r"(r2), "=r"(r3) : "r"(addr))

__device__ __forceinline__ void mma_bf16(float* c, const unsigned* a, const unsigned* b) {
    asm volatile(
        "mma.sync.aligned.m16n8k16.row.col.f32.bf16.bf16.f32 "
        "{%0,%1,%2,%3}, {%4,%5,%6,%7}, {%8,%9}, {%0,%1,%2,%3};"
        : "+f"(c[0]), "+f"(c[1]), "+f"(c[2]), "+f"(c[3])
        : "r"(a[0]), "r"(a[1]), "r"(a[2]), "r"(a[3]), "r"(b[0]), "r"(b[1]));
}

// ---------------------------------------------------------------------------
// Kernel P: beta|alpha = seq @ [e_w | v_w] via bf16 3-pass mma. K=128, 1 stage.
// Grid (9, 32) x 256 thr. bx=0 -> beta (writes g_bT transposed bf16 hi/lo),
// bx>0 -> alpha cols (bx-1)*64 (writes g_alpha fp32).
// W is now split IN-KERNEL (wprep folded): fp32 W-block bounced through the
// A region of smem, transposed+split into P_WH/P_WL, then A staged over it.
// ---------------------------------------------------------------------------
__global__ void __launch_bounds__(256, 2) precompute_mma_kernel(
        const float* __restrict__ seq,
        const float* __restrict__ e_w,
        const float* __restrict__ v_w) {
    extern __shared__ __align__(16) char ps[];
    const unsigned sb = smem_u32(ps);

    const int tid = threadIdx.x;
    const int l = tid & 31;
    const int w = tid >> 5;
    const int wr = w >> 1;
    const int wc = w & 1;

    const int bx = blockIdx.x;
    const int by = blockIdx.y;
    const int n0 = by * 128;             // global seq row base

    // ---- phase 0: load fp32 W block [128 f][64 c] into bounce (A region)
    {
        const float* wsrc;
        int wstride, c0;
        if (bx == 0) { wsrc = e_w; wstride = Uq;      c0 = 0; }
        else         { wsrc = v_w; wstride = Mq * Uq; c0 = (bx - 1) * 64; }
        float* wb = (float*)ps;          // [128][WS]
#pragma unroll
        for (int it = 0; it < 8; it++) {
            int v = tid + it * 256;      // < 2048 float4
            int f = v >> 4, cq = (v & 15) * 4;
            float4 t = *(const float4*)&wsrc[f * wstride + c0 + cq];
            wb[f * WS + cq + 0] = t.x; wb[f * WS + cq + 1] = t.y;
            wb[f * WS + cq + 2] = t.z; wb[f * WS + cq + 3] = t.w;
        }
    }
    __syncthreads();

    // ---- phase 1: transpose + bf16 hi/lo split into P_WH / P_WL [c][f]
    {
        const float* wb = (const float*)ps;
        const int c = tid >> 2;          // 0..63
        const int fq8 = tid & 3;
#pragma unroll
        for (int it = 0; it < 4; it++) {
            int f0 = (fq8 + it * 4) * 8; // 0..120 step 8
            unsigned h[4], lo[4];
#pragma unroll
            for (int k = 0; k < 4; k++) {
                float a0 = wb[(f0 + 2 * k) * WS + c];
                float a1 = wb[(f0 + 2 * k + 1) * WS + c];
                h[k] = cvt_bf16x2(a0, a1);
                float r0 = a0 - bf_lo_f(h[k]);
                float r1 = a1 - bf_hi_f(h[k]);
                lo[k] = cvt_bf16x2(r0, r1);
            }
            unsigned off = (unsigned)c * SA2 + f0 * 2;
            *(uint4*)(ps + P_WH + off) = make_uint4(h[0], h[1], h[2], h[3]);
            *(uint4*)(ps + P_WL + off) = make_uint4(lo[0], lo[1], lo[2], lo[3]);
        }
    }
    __syncthreads();

    // ---- phase 2: stage A (seq 128 rows x 128 f) hi/lo bf16 over the bounce
#pragma unroll
    for (int it = 0; it < 16; it++) {
        int v = tid + it * 256;          // < 4096
        int r = v >> 5, fq = v & 31;
        float4 t = *(const float4*)&seq[(size_t)(n0 + r) * Fq + fq * 4];
        unsigned h0 = cvt_bf16x2(t.x, t.y), h1 = cvt_bf16x2(t.z, t.w);
        unsigned l0 = cvt_bf16x2(t.x - bf_lo_f(h0), t.y - bf_hi_f(h0));
        unsigned l1 = cvt_bf16x2(t.z - bf_lo_f(h1), t.w - bf_hi_f(h1));
        unsigned off = (unsigned)r * SA2 + fq * 8;
        *(uint2*)(ps + P_AH + off) = make_uint2(h0, h1);
        *(uint2*)(ps + P_AL + off) = make_uint2(l0, l1);
    }
    __syncthreads();

    float acc[2][4][4];
#pragma unroll
    for (int rt = 0; rt < 2; rt++)
#pragma unroll
        for (int nt = 0; nt < 4; nt++)
#pragma unroll
            for (int k = 0; k < 4; k++) acc[rt][nt][k] = 0.f;

    const unsigned aRow = (unsigned)(wr * 32 + (l & 15)) * SA2 + ((l >> 4) * 16);
    const unsigned bRow = (unsigned)(wc * 32 + (l & 7) + ((l >> 4) & 1) * 8) * SA2
                        + (((l >> 3) & 1) * 16);

#pragma unroll
    for (int ks = 0; ks < 8; ks++) {
        unsigned ah[2][4], al[2][4], bh[8], bl[8];
#pragma unroll
        for (int rt = 0; rt < 2; rt++) {
            unsigned aoff = aRow + (unsigned)rt * 16 * SA2 + ks * 32;
            LDSM4(ah[rt][0], ah[rt][1], ah[rt][2], ah[rt][3], sb + P_AH + aoff);
            LDSM4(al[rt][0], al[rt][1], al[rt][2], al[rt][3], sb + P_AL + aoff);
        }
#pragma unroll
        for (int g = 0; g < 2; g++) {
            unsigned boff = bRow + (unsigned)g * 16 * SA2 + ks * 32;
            LDSM4(bh[g*4+0], bh[g*4+1], bh[g*4+2], bh[g*4+3], sb + P_WH + boff);
            LDSM4(bl[g*4+0], bl[g*4+1], bl[g*4+2], bl[g*4+3], sb + P_WL + boff);
        }
#pragma unroll
        for (int rt = 0; rt < 2; rt++)
#pragma unroll
            for (int nt = 0; nt < 4; nt++) {
                mma_bf16(acc[rt][nt], ah[rt], &bh[nt * 2]);
                mma_bf16(acc[rt][nt], al[rt], &bh[nt * 2]);
                mma_bf16(acc[rt][nt], ah[rt], &bl[nt * 2]);
            }
    }

    if (bx > 0) {
        // alpha: write fp32, cols (bx-1)*64 of the 512 (m,u) columns
        const int c0 = (bx - 1) * 64;
#pragma unroll
        for (int rt = 0; rt < 2; rt++) {
            const int r0 = n0 + wr * 32 + rt * 16 + (l >> 2);
#pragma unroll
            for (int nt = 0; nt < 4; nt++) {
                const int cu = c0 + wc * 32 + nt * 8 + (l & 3) * 2;
                const size_t idx0 = (size_t)r0 * (Mq * Uq) + cu;
                const size_t idx8 = idx0 + 8 * (Mq * Uq);
                *(float2*)&g_alpha[idx0] = make_float2(acc[rt][nt][0], acc[rt][nt][1]);
                *(float2*)&g_alpha[idx8] = make_float2(acc[rt][nt][2], acc[rt][nt][3]);
            }
        }
    } else {
        // beta: bounce C through smem, emit transposed bf16 hi/lo [b][u][n]
        __syncthreads();                 // smem A/W no longer needed
        float* cs = (float*)ps;          // [128][CS]
#pragma unroll
        for (int rt = 0; rt < 2; rt++) {
            const int r0 = wr * 32 + rt * 16 + (l >> 2);
#pragma unroll
            for (int nt = 0; nt < 4; nt++) {
                const int u = wc * 32 + nt * 8 + (l & 3) * 2;
                *(float2*)&cs[r0 * CS + u] = make_float2(acc[rt][nt][0], acc[rt][nt][1]);
                *(float2*)&cs[(r0 + 8) * CS + u] = make_float2(acc[rt][nt][2], acc[rt][nt][3]);
            }
        }
        __syncthreads();
        const int b   = n0 >> 11;
        const int nin = n0 & 2047;
        const int u  = tid >> 2;         // 0..63
        const int nq = tid & 3;
#pragma unroll
        for (int it = 0; it < 8; it++) {
            int n = nq * 4 + it * 16;
            float v0 = cs[(n + 0) * CS + u], v1 = cs[(n + 1) * CS + u];
            float v2 = cs[(n + 2) * CS + u], v3 = cs[(n + 3) * CS + u];
            unsigned h01 = cvt_bf16x2(v0, v1), h23 = cvt_bf16x2(v2, v3);
            unsigned l01 = cvt_bf16x2(v0 - bf_lo_f(h01), v1 - bf_hi_f(h01));
            unsigned l23 = cvt_bf16x2(v2 - bf_lo_f(h23), v3 - bf_hi_f(h23));
            size_t idx = (size_t)(b * Uq + u) * Nq + nin + n;
            *(uint2*)&g_bTh[idx] = make_uint2(h01, h23);
            *(uint2*)&g_bTl[idx] = make_uint2(l01, l23);
        }
    }
}

// ---------------------------------------------------------------------------
// Kernel B (main): UNCHANGED (fused, double-buffered, 3-pass bf16 mma).
// At ~95% of the rt16 tensor-issue wall (103 us model).
// ---------------------------------------------------------------------------
__global__ void __launch_bounds__(256, 2) multigraph_mma_kernel(
        const float* __restrict__ graph,
        float* __restrict__ out) {
    extern __shared__ __align__(16) char smem[];
    const unsigned sb = smem_u32(smem);

    const int tid = threadIdx.x;
    const int l = tid & 31;
    const int w = tid >> 5;
    const int wr = w >> 1;
    const int wc = w & 1;

    const int rt0 = blockIdx.x * 128;
    const int b   = blockIdx.y;
    const int i0  = rt0 >> 3;

    const int rem = tid & 127;
    const int jj  = rem >> 1;
    const int mh  = rem & 1;
    const int odd = jj & 1;
    const int ilb = tid >> 7;
    const int jec = (jj & ~1) * 2;
    const int bu  = tid >> 3;
    const int bjq = tid & 7;

    float acc[2][4][4];
#pragma unroll
    for (int rt = 0; rt < 2; rt++)
#pragma unroll
        for (int nt = 0; nt < 4; nt++)
#pragma unroll
            for (int k = 0; k < 4; k++) acc[rt][nt][k] = 0.f;

    const unsigned aRow = (unsigned)(wr * 32 + (l & 15)) * SA + ((l >> 4) * 16);
    const unsigned bRow = (unsigned)(wc * 32 + (l & 7) + ((l >> 4) & 1) * 8) * SA
                        + (((l >> 3) & 1) * 16);

    const size_t gbase = ((size_t)b * Nq + i0) * Nq * Mq;
    const size_t bTb = (size_t)b * Uq * Nq;

    float4 av[4];
    uint4 bhv[2], blv[2];

    auto ldgA = [&](int s, int h) {
        const int j0 = s * JC;
#pragma unroll
        for (int c = 0; c < 4; c++) {
            int il = (h * 4 + c) * 2 + ilb;
            av[c] = *(const float4*)(graph + gbase
                        + ((size_t)il * Nq + j0 + jj) * Mq + mh * 4);
        }
    };
    auto stsA = [&](int p, int h) {
        char* buf = smem + p * BUF_SZ;
#pragma unroll
        for (int c = 0; c < 4; c++) {
            int il = (h * 4 + c) * 2 + ilb;
            float4 own = av[c];
            float4 rcv;
            rcv.x = __shfl_xor_sync(0xffffffffu, own.x, 2);
            rcv.y = __shfl_xor_sync(0xffffffffu, own.y, 2);
            rcv.z = __shfl_xor_sync(0xffffffffu, own.z, 2);
            rcv.w = __shfl_xor_sync(0xffffffffu, own.w, 2);
            const float* pje = odd ? (const float*)&rcv : (const float*)&own;
            const float* pjo = odd ? (const float*)&own : (const float*)&rcv;
#pragma unroll
            for (int k = 0; k < 2; k++) {
                int q = odd * 2 + k;
                unsigned row = (unsigned)(il * 8 + mh * 4 + q);
                unsigned h2 = cvt_bf16x2(pje[q], pjo[q]);
                float r0 = pje[q] - bf_lo_f(h2);
                float r1 = pjo[q] - bf_hi_f(h2);
                unsigned lo = cvt_bf16x2(r0, r1);
                *(unsigned*)(buf + AH_OFF + row * SA + jec) = h2;
                *(unsigned*)(buf + AL_OFF + row * SA + jec) = lo;
            }
        }
    };
    auto ldgB = [&](int s) {
        const int j0 = s * JC;
        size_t src = bTb + (size_t)bu * Nq + j0 + bjq * 8;
        bhv[0] = *(const uint4*)&g_bTh[src];
        blv[0] = *(const uint4*)&g_bTl[src];
        src += (size_t)32 * Nq;
        bhv[1] = *(const uint4*)&g_bTh[src];
        blv[1] = *(const uint4*)&g_bTl[src];
    };
    auto stsB = [&](int p) {
        char* buf = smem + p * BUF_SZ;
#pragma unroll
        for (int k = 0; k < 2; k++) {
            unsigned off = (unsigned)(bu + k * 32) * SA + bjq * 16;
            *(uint4*)(buf + BH_OFF + off) = bhv[k];
            *(uint4*)(buf + BL_OFF + off) = blv[k];
        }
    };
    auto mmaHalf = [&](int p, int ks0) {
        const unsigned base = sb + (unsigned)p * BUF_SZ;
#pragma unroll
        for (int ks = ks0; ks < ks0 + 2; ks++) {
            unsigned ah[2][4], al[2][4], bh[8], bl[8];
#pragma unroll
            for (int rt = 0; rt < 2; rt++) {
                unsigned aoff = aRow + (unsigned)rt * 16 * SA + ks * 32;
                LDSM4(ah[rt][0], ah[rt][1], ah[rt][2], ah[rt][3], base + AH_OFF + aoff);
                LDSM4(al[rt][0], al[rt][1], al[rt][2], al[rt][3], base + AL_OFF + aoff);
            }
#pragma unroll
            for (int g = 0; g < 2; g++) {
                unsigned boff = bRow + (unsigned)g * 16 * SA + ks * 32;
                LDSM4(bh[g*4+0], bh[g*4+1], bh[g*4+2], bh[g*4+3], base + BH_OFF + boff);
                LDSM4(bl[g*4+0], bl[g*4+1], bl[g*4+2], bl[g*4+3], base + BL_OFF + boff);
            }
#pragma unroll
            for (int rt = 0; rt < 2; rt++)
#pragma unroll
                for (int nt = 0; nt < 4; nt++) {
                    mma_bf16(acc[rt][nt], ah[rt], &bh[nt * 2]);
                    mma_bf16(acc[rt][nt], al[rt], &bh[nt * 2]);
                    mma_bf16(acc[rt][nt], ah[rt], &bl[nt * 2]);
                }
        }
    };

    ldgB(0);
    ldgA(0, 0); stsA(0, 0);
    ldgA(0, 1); stsA(0, 1);
    stsB(0);

#pragma unroll 1
    for (int s = 0; s < NSTAGE; s++) {
        __syncthreads();
        const int p = s & 1, pn = p ^ 1;
        if (s + 1 < NSTAGE) { ldgB(s + 1); ldgA(s + 1, 0); }
        mmaHalf(p, 0);
        if (s + 1 < NSTAGE) { stsA(pn, 0); ldgA(s + 1, 1); }
        mmaHalf(p, 2);
        if (s + 1 < NSTAGE) { stsA(pn, 1); stsB(pn); }
    }

#pragma unroll
    for (int rt = 0; rt < 2; rt++) {
        const int r0 = rt0 + wr * 32 + rt * 16 + (l >> 2);
#pragma unroll
        for (int nt = 0; nt < 4; nt++) {
            const int u = wc * 32 + nt * 8 + (l & 3) * 2;
            const size_t idx0 = ((size_t)b * NM + r0) * Uq + u;
            const size_t idx8 = idx0 + 8 * Uq;
            float2 a0 = *(const float2*)&g_alpha[idx0];
            float2 a1 = *(const float2*)&g_alpha[idx8];
            float2 o0, o1;
            o0.x = 1.0f / (1.0f + __expf(-(acc[rt][nt][0] + a0.x)));
            o0.y = 1.0f / (1.0f + __expf(-(acc[rt][nt][1] + a0.y)));
            o1.x = 1.0f / (1.0f + __expf(-(acc[rt][nt][2] + a1.x)));
            o1.y = 1.0f / (1.0f + __expf(-(acc[rt][nt][3] + a1.y)));
            *(float2*)&out[idx0] = o0;
            *(float2*)&out[idx8] = o1;
        }
    }
}

// ---------------------------------------------------------------------------
extern "C" void kernel_launch(void* const* d_in, const int* in_sizes, int n_in,
                              void* d_out, int out_size) {
    const float* seq   = (const float*)d_in[0];   // (B,N,F)
    const float* graph = (const float*)d_in[1];   // (B,N,N,M)
    const float* e_w   = (const float*)d_in[2];   // (F,U)
    const float* v_w   = (const float*)d_in[3];   // (F,M,U)
    float* out = (float*)d_out;                   // (B,N,M,U)

    cudaFuncSetAttribute(precompute_mma_kernel,
                         cudaFuncAttributeMaxDynamicSharedMemorySize, SMEM_PRE);
    cudaFuncSetAttribute(multigraph_mma_kernel,
                         cudaFuncAttributeMaxDynamicSharedMemorySize, SMEM_MAIN);

    dim3 gridP(9, 32);
    precompute_mma_kernel<<<gridP, 256, SMEM_PRE>>>(seq, e_w, v_w);

    dim3 gridB(128, Bq);
    multigraph_mma_kernel<<<gridB, 256, SMEM_MAIN>>>(graph, out);
    (void)in_sizes; (void)n_in; (void)out_size;
}

// round 11
// speedup vs baseline: 1.3951x; 1.1050x over previous
#include <cuda_runtime.h>
#include <cuda_bf16.h>
#include <math.h>

#define Bq 2
#define Nq 2048
#define Fq 128
#define Mq 8
#define Uq 64
#define NM (Nq * Mq)            // 16384 rows of A'
#define OUTSZ (Bq * Nq * Mq * Uq)

#define JC 32                   // j per stage (main)
#define NSTAGE (Nq / JC)        // 64

// ---- main kernel smem: ring of 3 buffers.
// A: 128 rows x 32 j bf16 (64B data, stride 80) hi+lo; B: 64 u x 32 j hi+lo.
#define SA 80
#define AH_OFF 0
#define AL_OFF (AH_OFF + 128 * SA)      // 10240
#define BH_OFF (AL_OFF + 128 * SA)      // 20480
#define BL_OFF (BH_OFF + 64 * SA)       // 25600
#define BUF_SZ (BL_OFF + 64 * SA)       // 30720
#define SMEM_MAIN (3 * BUF_SZ)          // 92160

// ---- precompute-mma smem (unchanged)
#define SA2 272
#define P_AH 0
#define P_AL (P_AH + 128 * SA2)
#define P_WH (P_AL + 128 * SA2)
#define P_WL (P_WH + 64 * SA2)
#define SMEM_PRE (P_WL + 64 * SA2)      // 104448
#define CS 66
#define WS 69

// device scratch (allocation-free rule)
__device__ float g_alpha[OUTSZ];
__device__ unsigned short g_bTh[Bq * Uq * Nq];   // betaT hi bf16 [b][u][n]
__device__ unsigned short g_bTl[Bq * Uq * Nq];   // betaT lo bf16

__device__ __forceinline__ unsigned smem_u32(const void* p) {
    unsigned r;
    asm("{ .reg .u64 t; cvta.to.shared.u64 t, %1; cvt.u32.u64 %0, t; }"
        : "=r"(r) : "l"(p));
    return r;
}
__device__ __forceinline__ unsigned cvt_bf16x2(float lo_elem, float hi_elem) {
    unsigned r;   // low 16 bits <- lo_elem, high <- hi_elem
    asm("cvt.rn.bf16x2.f32 %0, %1, %2;" : "=r"(r) : "f"(hi_elem), "f"(lo_elem));
    return r;
}
__device__ __forceinline__ float bf_lo_f(unsigned h) { return __uint_as_float(h << 16); }
__device__ __forceinline__ float bf_hi_f(unsigned h) { return __uint_as_float(h & 0xffff0000u); }

#define LDSM4(r0, r1, r2, r3, addr) \
    asm volatile("ldmatrix.sync.aligned.m8n8.x4.shared.b16 {%0,%1,%2,%3}, [%4];" \
                 : "=r"(r0), "=r"(r1), "=r"(r2), "=r"(r3) : "r"(addr))

__device__ __forceinline__ void mma_bf16(float* c, const unsigned* a, const unsigned* b) {
    asm volatile(
        "mma.sync.aligned.m16n8k16.row.col.f32.bf16.bf16.f32 "
        "{%0,%1,%2,%3}, {%4,%5,%6,%7}, {%8,%9}, {%0,%1,%2,%3};"
        : "+f"(c[0]), "+f"(c[1]), "+f"(c[2]), "+f"(c[3])
        : "r"(a[0]), "r"(a[1]), "r"(a[2]), "r"(a[3]), "r"(b[0]), "r"(b[1]));
}

// ---------------------------------------------------------------------------
// Kernel P: beta|alpha = seq @ [e_w | v_w]  (UNCHANGED from round 10)
// ---------------------------------------------------------------------------
__global__ void __launch_bounds__(256, 2) precompute_mma_kernel(
        const float* __restrict__ seq,
        const float* __restrict__ e_w,
        const float* __restrict__ v_w) {
    extern __shared__ __align__(16) char ps[];
    const unsigned sb = smem_u32(ps);

    const int tid = threadIdx.x;
    const int l = tid & 31;
    const int w = tid >> 5;
    const int wr = w >> 1;
    const int wc = w & 1;

    const int bx = blockIdx.x;
    const int by = blockIdx.y;
    const int n0 = by * 128;

    {
        const float* wsrc;
        int wstride, c0;
        if (bx == 0) { wsrc = e_w; wstride = Uq;      c0 = 0; }
        else         { wsrc = v_w; wstride = Mq * Uq; c0 = (bx - 1) * 64; }
        float* wb = (float*)ps;
#pragma unroll
        for (int it = 0; it < 8; it++) {
            int v = tid + it * 256;
            int f = v >> 4, cq = (v & 15) * 4;
            float4 t = *(const float4*)&wsrc[f * wstride + c0 + cq];
            wb[f * WS + cq + 0] = t.x; wb[f * WS + cq + 1] = t.y;
            wb[f * WS + cq + 2] = t.z; wb[f * WS + cq + 3] = t.w;
        }
    }
    __syncthreads();

    {
        const float* wb = (const float*)ps;
        const int c = tid >> 2;
        const int fq8 = tid & 3;
#pragma unroll
        for (int it = 0; it < 4; it++) {
            int f0 = (fq8 + it * 4) * 8;
            unsigned h[4], lo[4];
#pragma unroll
            for (int k = 0; k < 4; k++) {
                float a0 = wb[(f0 + 2 * k) * WS + c];
                float a1 = wb[(f0 + 2 * k + 1) * WS + c];
                h[k] = cvt_bf16x2(a0, a1);
                float r0 = a0 - bf_lo_f(h[k]);
                float r1 = a1 - bf_hi_f(h[k]);
                lo[k] = cvt_bf16x2(r0, r1);
            }
            unsigned off = (unsigned)c * SA2 + f0 * 2;
            *(uint4*)(ps + P_WH + off) = make_uint4(h[0], h[1], h[2], h[3]);
            *(uint4*)(ps + P_WL + off) = make_uint4(lo[0], lo[1], lo[2], lo[3]);
        }
    }
    __syncthreads();

#pragma unroll
    for (int it = 0; it < 16; it++) {
        int v = tid + it * 256;
        int r = v >> 5, fq = v & 31;
        float4 t = *(const float4*)&seq[(size_t)(n0 + r) * Fq + fq * 4];
        unsigned h0 = cvt_bf16x2(t.x, t.y), h1 = cvt_bf16x2(t.z, t.w);
        unsigned l0 = cvt_bf16x2(t.x - bf_lo_f(h0), t.y - bf_hi_f(h0));
        unsigned l1 = cvt_bf16x2(t.z - bf_lo_f(h1), t.w - bf_hi_f(h1));
        unsigned off = (unsigned)r * SA2 + fq * 8;
        *(uint2*)(ps + P_AH + off) = make_uint2(h0, h1);
        *(uint2*)(ps + P_AL + off) = make_uint2(l0, l1);
    }
    __syncthreads();

    float acc[2][4][4];
#pragma unroll
    for (int rt = 0; rt < 2; rt++)
#pragma unroll
        for (int nt = 0; nt < 4; nt++)
#pragma unroll
            for (int k = 0; k < 4; k++) acc[rt][nt][k] = 0.f;

    const unsigned aRow = (unsigned)(wr * 32 + (l & 15)) * SA2 + ((l >> 4) * 16);
    const unsigned bRow = (unsigned)(wc * 32 + (l & 7) + ((l >> 4) & 1) * 8) * SA2
                        + (((l >> 3) & 1) * 16);

#pragma unroll
    for (int ks = 0; ks < 8; ks++) {
        unsigned ah[2][4], al[2][4], bh[8], bl[8];
#pragma unroll
        for (int rt = 0; rt < 2; rt++) {
            unsigned aoff = aRow + (unsigned)rt * 16 * SA2 + ks * 32;
            LDSM4(ah[rt][0], ah[rt][1], ah[rt][2], ah[rt][3], sb + P_AH + aoff);
            LDSM4(al[rt][0], al[rt][1], al[rt][2], al[rt][3], sb + P_AL + aoff);
        }
#pragma unroll
        for (int g = 0; g < 2; g++) {
            unsigned boff = bRow + (unsigned)g * 16 * SA2 + ks * 32;
            LDSM4(bh[g*4+0], bh[g*4+1], bh[g*4+2], bh[g*4+3], sb + P_WH + boff);
            LDSM4(bl[g*4+0], bl[g*4+1], bl[g*4+2], bl[g*4+3], sb + P_WL + boff);
        }
#pragma unroll
        for (int rt = 0; rt < 2; rt++)
#pragma unroll
            for (int nt = 0; nt < 4; nt++) {
                mma_bf16(acc[rt][nt], ah[rt], &bh[nt * 2]);
                mma_bf16(acc[rt][nt], al[rt], &bh[nt * 2]);
                mma_bf16(acc[rt][nt], ah[rt], &bl[nt * 2]);
            }
    }

    if (bx > 0) {
        const int c0 = (bx - 1) * 64;
#pragma unroll
        for (int rt = 0; rt < 2; rt++) {
            const int r0 = n0 + wr * 32 + rt * 16 + (l >> 2);
#pragma unroll
            for (int nt = 0; nt < 4; nt++) {
                const int cu = c0 + wc * 32 + nt * 8 + (l & 3) * 2;
                const size_t idx0 = (size_t)r0 * (Mq * Uq) + cu;
                const size_t idx8 = idx0 + 8 * (Mq * Uq);
                *(float2*)&g_alpha[idx0] = make_float2(acc[rt][nt][0], acc[rt][nt][1]);
                *(float2*)&g_alpha[idx8] = make_float2(acc[rt][nt][2], acc[rt][nt][3]);
            }
        }
    } else {
        __syncthreads();
        float* cs = (float*)ps;
#pragma unroll
        for (int rt = 0; rt < 2; rt++) {
            const int r0 = wr * 32 + rt * 16 + (l >> 2);
#pragma unroll
            for (int nt = 0; nt < 4; nt++) {
                const int u = wc * 32 + nt * 8 + (l & 3) * 2;
                *(float2*)&cs[r0 * CS + u] = make_float2(acc[rt][nt][0], acc[rt][nt][1]);
                *(float2*)&cs[(r0 + 8) * CS + u] = make_float2(acc[rt][nt][2], acc[rt][nt][3]);
            }
        }
        __syncthreads();
        const int b   = n0 >> 11;
        const int nin = n0 & 2047;
        const int u  = tid >> 2;
        const int nq = tid & 3;
#pragma unroll
        for (int it = 0; it < 8; it++) {
            int n = nq * 4 + it * 16;
            float v0 = cs[(n + 0) * CS + u], v1 = cs[(n + 1) * CS + u];
            float v2 = cs[(n + 2) * CS + u], v3 = cs[(n + 3) * CS + u];
            unsigned h01 = cvt_bf16x2(v0, v1), h23 = cvt_bf16x2(v2, v3);
            unsigned l01 = cvt_bf16x2(v0 - bf_lo_f(h01), v1 - bf_hi_f(h01));
            unsigned l23 = cvt_bf16x2(v2 - bf_lo_f(h23), v3 - bf_hi_f(h23));
            size_t idx = (size_t)(b * Uq + u) * Nq + nin + n;
            *(uint2*)&g_bTh[idx] = make_uint2(h01, h23);
            *(uint2*)&g_bTl[idx] = make_uint2(l01, l23);
        }
    }
}

// ---------------------------------------------------------------------------
// Kernel B (main): 3-stage ring pipeline, JC=32.
// Per stage: sync -> STS(s+1 from regs loaded last iter) -> LDG(s+2) -> mma(s).
// LDG gets a full stage (~1500 cyc) before its STS: no exposed DRAM latency.
// ---------------------------------------------------------------------------
__global__ void __launch_bounds__(256, 2) multigraph_mma_kernel(
        const float* __restrict__ graph,
        float* __restrict__ out) {
    extern __shared__ __align__(16) char smem[];
    const unsigned sb = smem_u32(smem);

    const int tid = threadIdx.x;
    const int l = tid & 31;
    const int w = tid >> 5;
    const int wr = w >> 1;                   // 0..3 (32 rows)
    const int wc = w & 1;                    // 0..1 (32 u)

    const int rt0 = blockIdx.x * 128;        // global A' row base
    const int b   = blockIdx.y;
    const int i0  = rt0 >> 3;

    // A staging: thread covers (jp, mh) for 4 il values
    const int jp  = (tid >> 1) & 31;         // j within stage
    const int mh  = tid & 1;                 // m-half
    const int odd = jp & 1;
    const int ilg = tid >> 6;                // 0..3
    const int jec = (jp & ~1) * 2;           // byte col of j-pair word
    // B staging: one uint4 hi + lo per thread
    const int bu  = tid >> 2;                // 0..63
    const int bjq = tid & 3;

    float acc[2][4][4];
#pragma unroll
    for (int rt = 0; rt < 2; rt++)
#pragma unroll
        for (int nt = 0; nt < 4; nt++)
#pragma unroll
            for (int k = 0; k < 4; k++) acc[rt][nt][k] = 0.f;

    const unsigned aRow = (unsigned)(wr * 32 + (l & 15)) * SA + ((l >> 4) * 16);
    const unsigned bRow = (unsigned)(wc * 32 + (l & 7) + ((l >> 4) & 1) * 8) * SA
                        + (((l >> 3) & 1) * 16);

    const size_t gbase = ((size_t)b * Nq + i0) * Nq * Mq;
    const size_t bTb = (size_t)b * Uq * Nq;

    float4 av[4];
    uint4 bhv, blv;

    auto ldgA = [&](int s) {
        const int j0 = s * JC;
#pragma unroll
        for (int c = 0; c < 4; c++) {
            int il = c * 4 + ilg;
            av[c] = *(const float4*)(graph + gbase
                        + ((size_t)il * Nq + j0 + jp) * Mq + mh * 4);
        }
    };
    auto ldgB = [&](int s) {
        const int j0 = s * JC;
        size_t src = bTb + (size_t)bu * Nq + j0 + bjq * 8;
        bhv = *(const uint4*)&g_bTh[src];
        blv = *(const uint4*)&g_bTl[src];
    };
    auto stsAB = [&](int p) {
        char* buf = smem + p * BUF_SZ;
#pragma unroll
        for (int c = 0; c < 4; c++) {
            int il = c * 4 + ilg;
            float4 own = av[c];
            float4 rcv;
            rcv.x = __shfl_xor_sync(0xffffffffu, own.x, 2);
            rcv.y = __shfl_xor_sync(0xffffffffu, own.y, 2);
            rcv.z = __shfl_xor_sync(0xffffffffu, own.z, 2);
            rcv.w = __shfl_xor_sync(0xffffffffu, own.w, 2);
            const float* pje = odd ? (const float*)&rcv : (const float*)&own;
            const float* pjo = odd ? (const float*)&own : (const float*)&rcv;
#pragma unroll
            for (int k = 0; k < 2; k++) {
                int q = odd * 2 + k;               // m index within quad
                unsigned row = (unsigned)(il * 8 + mh * 4 + q);
                unsigned h2 = cvt_bf16x2(pje[q], pjo[q]);
                float r0 = pje[q] - bf_lo_f(h2);
                float r1 = pjo[q] - bf_hi_f(h2);
                unsigned lo = cvt_bf16x2(r0, r1);
                *(unsigned*)(buf + AH_OFF + row * SA + jec) = h2;
                *(unsigned*)(buf + AL_OFF + row * SA + jec) = lo;
            }
        }
        *(uint4*)(buf + BH_OFF + (unsigned)bu * SA + bjq * 16) = bhv;
        *(uint4*)(buf + BL_OFF + (unsigned)bu * SA + bjq * 16) = blv;
    };
    auto mmaStage = [&](int p) {
        const unsigned base = sb + (unsigned)p * BUF_SZ;
#pragma unroll
        for (int ks = 0; ks < 2; ks++) {
            unsigned ah[2][4], al[2][4], bh[8], bl[8];
#pragma unroll
            for (int rt = 0; rt < 2; rt++) {
                unsigned aoff = aRow + (unsigned)rt * 16 * SA + ks * 32;
                LDSM4(ah[rt][0], ah[rt][1], ah[rt][2], ah[rt][3], base + AH_OFF + aoff);
                LDSM4(al[rt][0], al[rt][1], al[rt][2], al[rt][3], base + AL_OFF + aoff);
            }
#pragma unroll
            for (int g = 0; g < 2; g++) {
                unsigned boff = bRow + (unsigned)g * 16 * SA + ks * 32;
                LDSM4(bh[g*4+0], bh[g*4+1], bh[g*4+2], bh[g*4+3], base + BH_OFF + boff);
                LDSM4(bl[g*4+0], bl[g*4+1], bl[g*4+2], bl[g*4+3], base + BL_OFF + boff);
            }
#pragma unroll
            for (int rt = 0; rt < 2; rt++)
#pragma unroll
                for (int nt = 0; nt < 4; nt++) {
                    mma_bf16(acc[rt][nt], ah[rt], &bh[nt * 2]);
                    mma_bf16(acc[rt][nt], al[rt], &bh[nt * 2]);
                    mma_bf16(acc[rt][nt], ah[rt], &bl[nt * 2]);
                }
        }
    };

    // prologue: stage 0 staged; stage 1 in registers
    ldgA(0); ldgB(0);
    stsAB(0);
    ldgA(1); ldgB(1);

    int pm = 0;                              // buffer being mma'd (s%3)
    int pn = 1;                              // buffer being sts'd ((s+1)%3)
#pragma unroll 1
    for (int s = 0; s < NSTAGE; s++) {
        __syncthreads();
        if (s + 1 < NSTAGE) stsAB(pn);       // regs from last iter -> buf s+1
        if (s + 2 < NSTAGE) { ldgA(s + 2); ldgB(s + 2); }
        mmaStage(pm);
        pm = (pm == 2) ? 0 : pm + 1;
        pn = (pn == 2) ? 0 : pn + 1;
    }

    // fused epilogue: + alpha, sigmoid, store
#pragma unroll
    for (int rt = 0; rt < 2; rt++) {
        const int r0 = rt0 + wr * 32 + rt * 16 + (l >> 2);
#pragma unroll
        for (int nt = 0; nt < 4; nt++) {
            const int u = wc * 32 + nt * 8 + (l & 3) * 2;
            const size_t idx0 = ((size_t)b * NM + r0) * Uq + u;
            const size_t idx8 = idx0 + 8 * Uq;
            float2 a0 = *(const float2*)&g_alpha[idx0];
            float2 a1 = *(const float2*)&g_alpha[idx8];
            float2 o0, o1;
            o0.x = 1.0f / (1.0f + __expf(-(acc[rt][nt][0] + a0.x)));
            o0.y = 1.0f / (1.0f + __expf(-(acc[rt][nt][1] + a0.y)));
            o1.x = 1.0f / (1.0f + __expf(-(acc[rt][nt][2] + a1.x)));
            o1.y = 1.0f / (1.0f + __expf(-(acc[rt][nt][3] + a1.y)));
            *(float2*)&out[idx0] = o0;
            *(float2*)&out[idx8] = o1;
        }
    }
}

// ---------------------------------------------------------------------------
extern "C" void kernel_launch(void* const* d_in, const int* in_sizes, int n_in,
                              void* d_out, int out_size) {
    const float* seq   = (const float*)d_in[0];   // (B,N,F)
    const float* graph = (const float*)d_in[1];   // (B,N,N,M)
    const float* e_w   = (const float*)d_in[2];   // (F,U)
    const float* v_w   = (const float*)d_in[3];   // (F,M,U)
    float* out = (float*)d_out;                   // (B,N,M,U)

    cudaFuncSetAttribute(precompute_mma_kernel,
                         cudaFuncAttributeMaxDynamicSharedMemorySize, SMEM_PRE);
    cudaFuncSetAttribute(multigraph_mma_kernel,
                         cudaFuncAttributeMaxDynamicSharedMemorySize, SMEM_MAIN);

    dim3 gridP(9, 32);
    precompute_mma_kernel<<<gridP, 256, SMEM_PRE>>>(seq, e_w, v_w);

    dim3 gridB(128, Bq);
    multigraph_mma_kernel<<<gridB, 256, SMEM_MAIN>>>(graph, out);
    (void)in_sizes; (void)n_in; (void)out_size;
}

// round 12
// speedup vs baseline: 1.5792x; 1.1319x over previous
#include <cuda_runtime.h>
#include <cuda_bf16.h>
#include <math.h>

#define Bq 2
#define Nq 2048
#define Fq 128
#define Mq 8
#define Uq 64
#define NM (Nq * Mq)            // 16384 rows of A'
#define OUTSZ (Bq * Nq * Mq * Uq)

#define JC 32                   // j per stage (main)
#define NSTAGE (Nq / JC)        // 64

// ---- main kernel smem: ring of 3 buffers.
// A: j-major [32 j][128 rows] bf16 (256B data, stride 272) hi+lo.
// B: [64 u][32 j] bf16 (64B data, stride 80) hi+lo.
#define SAJ 272
#define SB 80
#define AH_OFF 0
#define AL_OFF (AH_OFF + 32 * SAJ)      //  8704
#define BH_OFF (AL_OFF + 32 * SAJ)      // 17408
#define BL_OFF (BH_OFF + 64 * SB)       // 22528
#define BUF_SZ (BL_OFF + 64 * SB)       // 27648
#define SMEM_MAIN (3 * BUF_SZ)          // 82944

// ---- precompute-mma smem (unchanged)
#define SA2 272
#define P_AH 0
#define P_AL (P_AH + 128 * SA2)
#define P_WH (P_AL + 128 * SA2)
#define P_WL (P_WH + 64 * SA2)
#define SMEM_PRE (P_WL + 64 * SA2)      // 104448
#define CS 66
#define WS 69

// device scratch (allocation-free rule)
__device__ float g_alpha[OUTSZ];
__device__ unsigned short g_bTh[Bq * Uq * Nq];   // betaT hi bf16 [b][u][n]
__device__ unsigned short g_bTl[Bq * Uq * Nq];   // betaT lo bf16

__device__ __forceinline__ unsigned smem_u32(const void* p) {
    unsigned r;
    asm("{ .reg .u64 t; cvta.to.shared.u64 t, %1; cvt.u32.u64 %0, t; }"
        : "=r"(r) : "l"(p));
    return r;
}
__device__ __forceinline__ unsigned cvt_bf16x2(float lo_elem, float hi_elem) {
    unsigned r;   // low 16 bits <- lo_elem, high <- hi_elem
    asm("cvt.rn.bf16x2.f32 %0, %1, %2;" : "=r"(r) : "f"(hi_elem), "f"(lo_elem));
    return r;
}
__device__ __forceinline__ float bf_lo_f(unsigned h) { return __uint_as_float(h << 16); }
__device__ __forceinline__ float bf_hi_f(unsigned h) { return __uint_as_float(h & 0xffff0000u); }

#define LDSM4(r0, r1, r2, r3, addr) \
    asm volatile("ldmatrix.sync.aligned.m8n8.x4.shared.b16 {%0,%1,%2,%3}, [%4];" \
                 : "=r"(r0), "=r"(r1), "=r"(r2), "=r"(r3) : "r"(addr))

#define LDSM4T(r0, r1, r2, r3, addr) \
    asm volatile("ldmatrix.sync.aligned.m8n8.x4.trans.shared.b16 {%0,%1,%2,%3}, [%4];" \
                 : "=r"(r0), "=r"(r1), "=r"(r2), "=r"(r3) : "r"(addr))

__device__ __forceinline__ void mma_bf16(float* c, const unsigned* a, const unsigned* b) {
    asm volatile(
        "mma.sync.aligned.m16n8k16.row.col.f32.bf16.bf16.f32 "
        "{%0,%1,%2,%3}, {%4,%5,%6,%7}, {%8,%9}, {%0,%1,%2,%3};"
        : "+f"(c[0]), "+f"(c[1]), "+f"(c[2]), "+f"(c[3])
        : "r"(a[0]), "r"(a[1]), "r"(a[2]), "r"(a[3]), "r"(b[0]), "r"(b[1]));
}

// ---------------------------------------------------------------------------
// Kernel P: beta|alpha = seq @ [e_w | v_w]  (UNCHANGED)
// ---------------------------------------------------------------------------
__global__ void __launch_bounds__(256, 2) precompute_mma_kernel(
        const float* __restrict__ seq,
        const float* __restrict__ e_w,
        const float* __restrict__ v_w) {
    extern __shared__ __align__(16) char ps[];
    const unsigned sb = smem_u32(ps);

    const int tid = threadIdx.x;
    const int l = tid & 31;
    const int w = tid >> 5;
    const int wr = w >> 1;
    const int wc = w & 1;

    const int bx = blockIdx.x;
    const int by = blockIdx.y;
    const int n0 = by * 128;

    {
        const float* wsrc;
        int wstride, c0;
        if (bx == 0) { wsrc = e_w; wstride = Uq;      c0 = 0; }
        else         { wsrc = v_w; wstride = Mq * Uq; c0 = (bx - 1) * 64; }
        float* wb = (float*)ps;
#pragma unroll
        for (int it = 0; it < 8; it++) {
            int v = tid + it * 256;
            int f = v >> 4, cq = (v & 15) * 4;
            float4 t = *(const float4*)&wsrc[f * wstride + c0 + cq];
            wb[f * WS + cq + 0] = t.x; wb[f * WS + cq + 1] = t.y;
            wb[f * WS + cq + 2] = t.z; wb[f * WS + cq + 3] = t.w;
        }
    }
    __syncthreads();

    {
        const float* wb = (const float*)ps;
        const int c = tid >> 2;
        const int fq8 = tid & 3;
#pragma unroll
        for (int it = 0; it < 4; it++) {
            int f0 = (fq8 + it * 4) * 8;
            unsigned h[4], lo[4];
#pragma unroll
            for (int k = 0; k < 4; k++) {
                float a0 = wb[(f0 + 2 * k) * WS + c];
                float a1 = wb[(f0 + 2 * k + 1) * WS + c];
                h[k] = cvt_bf16x2(a0, a1);
                float r0 = a0 - bf_lo_f(h[k]);
                float r1 = a1 - bf_hi_f(h[k]);
                lo[k] = cvt_bf16x2(r0, r1);
            }
            unsigned off = (unsigned)c * SA2 + f0 * 2;
            *(uint4*)(ps + P_WH + off) = make_uint4(h[0], h[1], h[2], h[3]);
            *(uint4*)(ps + P_WL + off) = make_uint4(lo[0], lo[1], lo[2], lo[3]);
        }
    }
    __syncthreads();

#pragma unroll
    for (int it = 0; it < 16; it++) {
        int v = tid + it * 256;
        int r = v >> 5, fq = v & 31;
        float4 t = *(const float4*)&seq[(size_t)(n0 + r) * Fq + fq * 4];
        unsigned h0 = cvt_bf16x2(t.x, t.y), h1 = cvt_bf16x2(t.z, t.w);
        unsigned l0 = cvt_bf16x2(t.x - bf_lo_f(h0), t.y - bf_hi_f(h0));
        unsigned l1 = cvt_bf16x2(t.z - bf_lo_f(h1), t.w - bf_hi_f(h1));
        unsigned off = (unsigned)r * SA2 + fq * 8;
        *(uint2*)(ps + P_AH + off) = make_uint2(h0, h1);
        *(uint2*)(ps + P_AL + off) = make_uint2(l0, l1);
    }
    __syncthreads();

    float acc[2][4][4];
#pragma unroll
    for (int rt = 0; rt < 2; rt++)
#pragma unroll
        for (int nt = 0; nt < 4; nt++)
#pragma unroll
            for (int k = 0; k < 4; k++) acc[rt][nt][k] = 0.f;

    const unsigned aRow = (unsigned)(wr * 32 + (l & 15)) * SA2 + ((l >> 4) * 16);
    const unsigned bRow = (unsigned)(wc * 32 + (l & 7) + ((l >> 4) & 1) * 8) * SA2
                        + (((l >> 3) & 1) * 16);

#pragma unroll
    for (int ks = 0; ks < 8; ks++) {
        unsigned ah[2][4], al[2][4], bh[8], bl[8];
#pragma unroll
        for (int rt = 0; rt < 2; rt++) {
            unsigned aoff = aRow + (unsigned)rt * 16 * SA2 + ks * 32;
            LDSM4(ah[rt][0], ah[rt][1], ah[rt][2], ah[rt][3], sb + P_AH + aoff);
            LDSM4(al[rt][0], al[rt][1], al[rt][2], al[rt][3], sb + P_AL + aoff);
        }
#pragma unroll
        for (int g = 0; g < 2; g++) {
            unsigned boff = bRow + (unsigned)g * 16 * SA2 + ks * 32;
            LDSM4(bh[g*4+0], bh[g*4+1], bh[g*4+2], bh[g*4+3], sb + P_WH + boff);
            LDSM4(bl[g*4+0], bl[g*4+1], bl[g*4+2], bl[g*4+3], sb + P_WL + boff);
        }
#pragma unroll
        for (int rt = 0; rt < 2; rt++)
#pragma unroll
            for (int nt = 0; nt < 4; nt++) {
                mma_bf16(acc[rt][nt], ah[rt], &bh[nt * 2]);
                mma_bf16(acc[rt][nt], al[rt], &bh[nt * 2]);
                mma_bf16(acc[rt][nt], ah[rt], &bl[nt * 2]);
            }
    }

    if (bx > 0) {
        const int c0 = (bx - 1) * 64;
#pragma unroll
        for (int rt = 0; rt < 2; rt++) {
            const int r0 = n0 + wr * 32 + rt * 16 + (l >> 2);
#pragma unroll
            for (int nt = 0; nt < 4; nt++) {
                const int cu = c0 + wc * 32 + nt * 8 + (l & 3) * 2;
                const size_t idx0 = (size_t)r0 * (Mq * Uq) + cu;
                const size_t idx8 = idx0 + 8 * (Mq * Uq);
                *(float2*)&g_alpha[idx0] = make_float2(acc[rt][nt][0], acc[rt][nt][1]);
                *(float2*)&g_alpha[idx8] = make_float2(acc[rt][nt][2], acc[rt][nt][3]);
            }
        }
    } else {
        __syncthreads();
        float* cs = (float*)ps;
#pragma unroll
        for (int rt = 0; rt < 2; rt++) {
            const int r0 = wr * 32 + rt * 16 + (l >> 2);
#pragma unroll
            for (int nt = 0; nt < 4; nt++) {
                const int u = wc * 32 + nt * 8 + (l & 3) * 2;
                *(float2*)&cs[r0 * CS + u] = make_float2(acc[rt][nt][0], acc[rt][nt][1]);
                *(float2*)&cs[(r0 + 8) * CS + u] = make_float2(acc[rt][nt][2], acc[rt][nt][3]);
            }
        }
        __syncthreads();
        const int b   = n0 >> 11;
        const int nin = n0 & 2047;
        const int u  = tid >> 2;
        const int nq = tid & 3;
#pragma unroll
        for (int it = 0; it < 8; it++) {
            int n = nq * 4 + it * 16;
            float v0 = cs[(n + 0) * CS + u], v1 = cs[(n + 1) * CS + u];
            float v2 = cs[(n + 2) * CS + u], v3 = cs[(n + 3) * CS + u];
            unsigned h01 = cvt_bf16x2(v0, v1), h23 = cvt_bf16x2(v2, v3);
            unsigned l01 = cvt_bf16x2(v0 - bf_lo_f(h01), v1 - bf_hi_f(h01));
            unsigned l23 = cvt_bf16x2(v2 - bf_lo_f(h23), v3 - bf_hi_f(h23));
            size_t idx = (size_t)(b * Uq + u) * Nq + nin + n;
            *(uint2*)&g_bTh[idx] = make_uint2(h01, h23);
            *(uint2*)&g_bTl[idx] = make_uint2(l01, l23);
        }
    }
}

// ---------------------------------------------------------------------------
// Kernel B (main): 3-stage ring, JC=32, A stored j-major + ldmatrix.trans.
// No shuffles: the 4 m-values of each loaded float4 are 4 consecutive rows
// at one j in [j][row] layout -> one STS.64 (hi) + one (lo) per cell.
// ---------------------------------------------------------------------------
__global__ void __launch_bounds__(256, 2) multigraph_mma_kernel(
        const float* __restrict__ graph,
        float* __restrict__ out) {
    extern __shared__ __align__(16) char smem[];
    const unsigned sb = smem_u32(smem);

    const int tid = threadIdx.x;
    const int l = tid & 31;
    const int w = tid >> 5;
    const int wr = w >> 1;                   // 0..3 (32 rows)
    const int wc = w & 1;                    // 0..1 (32 u)

    const int rt0 = blockIdx.x * 128;        // global A' row base
    const int b   = blockIdx.y;
    const int i0  = rt0 >> 3;

    // A staging: lane -> (jlo, mq); warp -> jhalf; thread covers 4 il
    const int mq  = tid & 1;
    const int jlo = (tid >> 1) & 15;
    const int jhalf = (tid >> 5) & 1;
    const int jp  = jhalf * 16 + jlo;        // 0..31
    const int ilg = tid >> 6;                // 0..3
    // B staging
    const int bu  = tid >> 2;                // 0..63
    const int bjq = tid & 3;

    float acc[2][4][4];
#pragma unroll
    for (int rt = 0; rt < 2; rt++)
#pragma unroll
        for (int nt = 0; nt < 4; nt++)
#pragma unroll
            for (int k = 0; k < 4; k++) acc[rt][nt][k] = 0.f;

    // A (trans) lane addressing: j = (l&7) + ((l>>4)&1)*8 ; row-chunk = (l>>3)&1
    const unsigned aRowT = (unsigned)((l & 7) + ((l >> 4) & 1) * 8) * SAJ
                         + (unsigned)(((l >> 3) & 1) * 16);
    const unsigned bRow = (unsigned)(wc * 32 + (l & 7) + ((l >> 4) & 1) * 8) * SB
                        + (((l >> 3) & 1) * 16);

    const size_t gbase = ((size_t)b * Nq + i0) * Nq * Mq;
    const size_t bTb = (size_t)b * Uq * Nq;

    float4 av[4];
    uint4 bhv, blv;

    auto ldgA = [&](int s) {
        const int j0 = s * JC;
#pragma unroll
        for (int c = 0; c < 4; c++) {
            int il = c * 4 + ilg;
            av[c] = *(const float4*)(graph + gbase
                        + ((size_t)il * Nq + j0 + jp) * Mq + mq * 4);
        }
    };
    auto ldgB = [&](int s) {
        const int j0 = s * JC;
        size_t src = bTb + (size_t)bu * Nq + j0 + bjq * 8;
        bhv = *(const uint4*)&g_bTh[src];
        blv = *(const uint4*)&g_bTl[src];
    };
    auto stsAB = [&](int p) {
        char* buf = smem + p * BUF_SZ;
#pragma unroll
        for (int c = 0; c < 4; c++) {
            int il = c * 4 + ilg;
            const float* v = (const float*)&av[c];
            unsigned h0 = cvt_bf16x2(v[0], v[1]);
            unsigned h1 = cvt_bf16x2(v[2], v[3]);
            unsigned l0 = cvt_bf16x2(v[0] - bf_lo_f(h0), v[1] - bf_hi_f(h0));
            unsigned l1 = cvt_bf16x2(v[2] - bf_lo_f(h1), v[3] - bf_hi_f(h1));
            unsigned off = (unsigned)jp * SAJ + (unsigned)(il * 8 + mq * 4) * 2;
            *(uint2*)(buf + AH_OFF + off) = make_uint2(h0, h1);
            *(uint2*)(buf + AL_OFF + off) = make_uint2(l0, l1);
        }
        *(uint4*)(buf + BH_OFF + (unsigned)bu * SB + bjq * 16) = bhv;
        *(uint4*)(buf + BL_OFF + (unsigned)bu * SB + bjq * 16) = blv;
    };
    auto mmaStage = [&](int p) {
        const unsigned base = sb + (unsigned)p * BUF_SZ;
#pragma unroll
        for (int ks = 0; ks < 2; ks++) {
            unsigned ah[2][4], al[2][4], bh[8], bl[8];
#pragma unroll
            for (int rt = 0; rt < 2; rt++) {
                unsigned aoff = aRowT + (unsigned)(ks * 16) * SAJ
                              + (unsigned)((wr * 32 + rt * 16) * 2);
                LDSM4T(ah[rt][0], ah[rt][1], ah[rt][2], ah[rt][3], base + AH_OFF + aoff);
                LDSM4T(al[rt][0], al[rt][1], al[rt][2], al[rt][3], base + AL_OFF + aoff);
            }
#pragma unroll
            for (int g = 0; g < 2; g++) {
                unsigned boff = bRow + (unsigned)g * 16 * SB + ks * 32;
                LDSM4(bh[g*4+0], bh[g*4+1], bh[g*4+2], bh[g*4+3], base + BH_OFF + boff);
                LDSM4(bl[g*4+0], bl[g*4+1], bl[g*4+2], bl[g*4+3], base + BL_OFF + boff);
            }
#pragma unroll
            for (int rt = 0; rt < 2; rt++)
#pragma unroll
                for (int nt = 0; nt < 4; nt++) {
                    mma_bf16(acc[rt][nt], ah[rt], &bh[nt * 2]);
                    mma_bf16(acc[rt][nt], al[rt], &bh[nt * 2]);
                    mma_bf16(acc[rt][nt], ah[rt], &bl[nt * 2]);
                }
        }
    };

    // prologue: stage 0 staged; stage 1 in registers
    ldgA(0); ldgB(0);
    stsAB(0);
    ldgA(1); ldgB(1);

    int pm = 0;                              // buffer being mma'd (s%3)
    int pn = 1;                              // buffer being sts'd ((s+1)%3)
#pragma unroll 1
    for (int s = 0; s < NSTAGE; s++) {
        __syncthreads();
        if (s + 1 < NSTAGE) stsAB(pn);       // regs from last iter -> buf s+1
        if (s + 2 < NSTAGE) { ldgA(s + 2); ldgB(s + 2); }
        mmaStage(pm);
        pm = (pm == 2) ? 0 : pm + 1;
        pn = (pn == 2) ? 0 : pn + 1;
    }

    // fused epilogue: + alpha, sigmoid, store
#pragma unroll
    for (int rt = 0; rt < 2; rt++) {
        const int r0 = rt0 + wr * 32 + rt * 16 + (l >> 2);
#pragma unroll
        for (int nt = 0; nt < 4; nt++) {
            const int u = wc * 32 + nt * 8 + (l & 3) * 2;
            const size_t idx0 = ((size_t)b * NM + r0) * Uq + u;
            const size_t idx8 = idx0 + 8 * Uq;
            float2 a0 = *(const float2*)&g_alpha[idx0];
            float2 a1 = *(const float2*)&g_alpha[idx8];
            float2 o0, o1;
            o0.x = 1.0f / (1.0f + __expf(-(acc[rt][nt][0] + a0.x)));
            o0.y = 1.0f / (1.0f + __expf(-(acc[rt][nt][1] + a0.y)));
            o1.x = 1.0f / (1.0f + __expf(-(acc[rt][nt][2] + a1.x)));
            o1.y = 1.0f / (1.0f + __expf(-(acc[rt][nt][3] + a1.y)));
            *(float2*)&out[idx0] = o0;
            *(float2*)&out[idx8] = o1;
        }
    }
}

// ---------------------------------------------------------------------------
extern "C" void kernel_launch(void* const* d_in, const int* in_sizes, int n_in,
                              void* d_out, int out_size) {
    const float* seq   = (const float*)d_in[0];   // (B,N,F)
    const float* graph = (const float*)d_in[1];   // (B,N,N,M)
    const float* e_w   = (const float*)d_in[2];   // (F,U)
    const float* v_w   = (const float*)d_in[3];   // (F,M,U)
    float* out = (float*)d_out;                   // (B,N,M,U)

    cudaFuncSetAttribute(precompute_mma_kernel,
                         cudaFuncAttributeMaxDynamicSharedMemorySize, SMEM_PRE);
    cudaFuncSetAttribute(multigraph_mma_kernel,
                         cudaFuncAttributeMaxDynamicSharedMemorySize, SMEM_MAIN);

    dim3 gridP(9, 32);
    precompute_mma_kernel<<<gridP, 256, SMEM_PRE>>>(seq, e_w, v_w);

    dim3 gridB(128, Bq);
    multigraph_mma_kernel<<<gridB, 256, SMEM_MAIN>>>(graph, out);
    (void)in_sizes; (void)n_in; (void)out_size;
}

// round 13
// speedup vs baseline: 1.5961x; 1.0107x over previous
#include <cuda_runtime.h>
#include <cuda_bf16.h>
#include <math.h>

#define Bq 2
#define Nq 2048
#define Fq 128
#define Mq 8
#define Uq 64
#define NM (Nq * Mq)            // 16384 rows of A'
#define OUTSZ (Bq * Nq * Mq * Uq)

#define JC 64                   // j per stage (main)
#define NSTAGE (Nq / JC)        // 32

// ---- main kernel smem: 2-buffer ring.
// A: j-major [64 j][128 rows bf16 = 256B, XOR-swizzled 16B chunks] hi+lo.
// B: [64 u][64 j bf16 = 128B data, stride 144] hi+lo (filled via cp.async).
#define SAJ 256
#define SBJ 144
#define AH_OFF 0
#define AL_OFF (AH_OFF + 64 * SAJ)      // 16384
#define BH_OFF (AL_OFF + 64 * SAJ)      // 32768
#define BL_OFF (BH_OFF + 64 * SBJ)      // 41984
#define BUF_SZ (BL_OFF + 64 * SBJ)      // 51200
#define SMEM_MAIN (2 * BUF_SZ)          // 102400

// ---- precompute-mma smem (unchanged)
#define SA2 272
#define P_AH 0
#define P_AL (P_AH + 128 * SA2)
#define P_WH (P_AL + 128 * SA2)
#define P_WL (P_WH + 64 * SA2)
#define SMEM_PRE (P_WL + 64 * SA2)      // 104448
#define CS 66
#define WS 69

// device scratch (allocation-free rule)
__device__ float g_alpha[OUTSZ];
__device__ unsigned short g_bTh[Bq * Uq * Nq];   // betaT hi bf16 [b][u][n]
__device__ unsigned short g_bTl[Bq * Uq * Nq];   // betaT lo bf16

__device__ __forceinline__ unsigned smem_u32(const void* p) {
    unsigned r;
    asm("{ .reg .u64 t; cvta.to.shared.u64 t, %1; cvt.u32.u64 %0, t; }"
        : "=r"(r) : "l"(p));
    return r;
}
__device__ __forceinline__ unsigned cvt_bf16x2(float lo_elem, float hi_elem) {
    unsigned r;   // low 16 bits <- lo_elem, high <- hi_elem
    asm("cvt.rn.bf16x2.f32 %0, %1, %2;" : "=r"(r) : "f"(hi_elem), "f"(lo_elem));
    return r;
}
__device__ __forceinline__ float bf_lo_f(unsigned h) { return __uint_as_float(h << 16); }
__device__ __forceinline__ float bf_hi_f(unsigned h) { return __uint_as_float(h & 0xffff0000u); }

#define LDSM4(r0, r1, r2, r3, addr) \
    asm volatile("ldmatrix.sync.aligned.m8n8.x4.shared.b16 {%0,%1,%2,%3}, [%4];" \
                 : "=r"(r0), "=r"(r1), "=r"(r2), "=r"(r3) : "r"(addr))

#define LDSM4T(r0, r1, r2, r3, addr) \
    asm volatile("ldmatrix.sync.aligned.m8n8.x4.trans.shared.b16 {%0,%1,%2,%3}, [%4];" \
                 : "=r"(r0), "=r"(r1), "=r"(r2), "=r"(r3) : "r"(addr))

#define CP_ASYNC16(dst, src) \
    asm volatile("cp.async.cg.shared.global [%0], [%1], 16;" :: "r"(dst), "l"(src))
#define CP_COMMIT() asm volatile("cp.async.commit_group;" ::: "memory")
#define CP_WAIT0()  asm volatile("cp.async.wait_group 0;" ::: "memory")

__device__ __forceinline__ void mma_bf16(float* c, const unsigned* a, const unsigned* b) {
    asm volatile(
        "mma.sync.aligned.m16n8k16.row.col.f32.bf16.bf16.f32 "
        "{%0,%1,%2,%3}, {%4,%5,%6,%7}, {%8,%9}, {%0,%1,%2,%3};"
        : "+f"(c[0]), "+f"(c[1]), "+f"(c[2]), "+f"(c[3])
        : "r"(a[0]), "r"(a[1]), "r"(a[2]), "r"(a[3]), "r"(b[0]), "r"(b[1]));
}

// ---------------------------------------------------------------------------
// Kernel P: beta|alpha = seq @ [e_w | v_w]  (UNCHANGED)
// ---------------------------------------------------------------------------
__global__ void __launch_bounds__(256, 2) precompute_mma_kernel(
        const float* __restrict__ seq,
        const float* __restrict__ e_w,
        const float* __restrict__ v_w) {
    extern __shared__ __align__(16) char ps[];
    const unsigned sb = smem_u32(ps);

    const int tid = threadIdx.x;
    const int l = tid & 31;
    const int w = tid >> 5;
    const int wr = w >> 1;
    const int wc = w & 1;

    const int bx = blockIdx.x;
    const int by = blockIdx.y;
    const int n0 = by * 128;

    {
        const float* wsrc;
        int wstride, c0;
        if (bx == 0) { wsrc = e_w; wstride = Uq;      c0 = 0; }
        else         { wsrc = v_w; wstride = Mq * Uq; c0 = (bx - 1) * 64; }
        float* wb = (float*)ps;
#pragma unroll
        for (int it = 0; it < 8; it++) {
            int v = tid + it * 256;
            int f = v >> 4, cq = (v & 15) * 4;
            float4 t = *(const float4*)&wsrc[f * wstride + c0 + cq];
            wb[f * WS + cq + 0] = t.x; wb[f * WS + cq + 1] = t.y;
            wb[f * WS + cq + 2] = t.z; wb[f * WS + cq + 3] = t.w;
        }
    }
    __syncthreads();

    {
        const float* wb = (const float*)ps;
        const int c = tid >> 2;
        const int fq8 = tid & 3;
#pragma unroll
        for (int it = 0; it < 4; it++) {
            int f0 = (fq8 + it * 4) * 8;
            unsigned h[4], lo[4];
#pragma unroll
            for (int k = 0; k < 4; k++) {
                float a0 = wb[(f0 + 2 * k) * WS + c];
                float a1 = wb[(f0 + 2 * k + 1) * WS + c];
                h[k] = cvt_bf16x2(a0, a1);
                float r0 = a0 - bf_lo_f(h[k]);
                float r1 = a1 - bf_hi_f(h[k]);
                lo[k] = cvt_bf16x2(r0, r1);
            }
            unsigned off = (unsigned)c * SA2 + f0 * 2;
            *(uint4*)(ps + P_WH + off) = make_uint4(h[0], h[1], h[2], h[3]);
            *(uint4*)(ps + P_WL + off) = make_uint4(lo[0], lo[1], lo[2], lo[3]);
        }
    }
    __syncthreads();

#pragma unroll
    for (int it = 0; it < 16; it++) {
        int v = tid + it * 256;
        int r = v >> 5, fq = v & 31;
        float4 t = *(const float4*)&seq[(size_t)(n0 + r) * Fq + fq * 4];
        unsigned h0 = cvt_bf16x2(t.x, t.y), h1 = cvt_bf16x2(t.z, t.w);
        unsigned l0 = cvt_bf16x2(t.x - bf_lo_f(h0), t.y - bf_hi_f(h0));
        unsigned l1 = cvt_bf16x2(t.z - bf_lo_f(h1), t.w - bf_hi_f(h1));
        unsigned off = (unsigned)r * SA2 + fq * 8;
        *(uint2*)(ps + P_AH + off) = make_uint2(h0, h1);
        *(uint2*)(ps + P_AL + off) = make_uint2(l0, l1);
    }
    __syncthreads();

    float acc[2][4][4];
#pragma unroll
    for (int rt = 0; rt < 2; rt++)
#pragma unroll
        for (int nt = 0; nt < 4; nt++)
#pragma unroll
            for (int k = 0; k < 4; k++) acc[rt][nt][k] = 0.f;

    const unsigned aRow = (unsigned)(wr * 32 + (l & 15)) * SA2 + ((l >> 4) * 16);
    const unsigned bRow = (unsigned)(wc * 32 + (l & 7) + ((l >> 4) & 1) * 8) * SA2
                        + (((l >> 3) & 1) * 16);

#pragma unroll
    for (int ks = 0; ks < 8; ks++) {
        unsigned ah[2][4], al[2][4], bh[8], bl[8];
#pragma unroll
        for (int rt = 0; rt < 2; rt++) {
            unsigned aoff = aRow + (unsigned)rt * 16 * SA2 + ks * 32;
            LDSM4(ah[rt][0], ah[rt][1], ah[rt][2], ah[rt][3], sb + P_AH + aoff);
            LDSM4(al[rt][0], al[rt][1], al[rt][2], al[rt][3], sb + P_AL + aoff);
        }
#pragma unroll
        for (int g = 0; g < 2; g++) {
            unsigned boff = bRow + (unsigned)g * 16 * SA2 + ks * 32;
            LDSM4(bh[g*4+0], bh[g*4+1], bh[g*4+2], bh[g*4+3], sb + P_WH + boff);
            LDSM4(bl[g*4+0], bl[g*4+1], bl[g*4+2], bl[g*4+3], sb + P_WL + boff);
        }
#pragma unroll
        for (int rt = 0; rt < 2; rt++)
#pragma unroll
            for (int nt = 0; nt < 4; nt++) {
                mma_bf16(acc[rt][nt], ah[rt], &bh[nt * 2]);
                mma_bf16(acc[rt][nt], al[rt], &bh[nt * 2]);
                mma_bf16(acc[rt][nt], ah[rt], &bl[nt * 2]);
            }
    }

    if (bx > 0) {
        const int c0 = (bx - 1) * 64;
#pragma unroll
        for (int rt = 0; rt < 2; rt++) {
            const int r0 = n0 + wr * 32 + rt * 16 + (l >> 2);
#pragma unroll
            for (int nt = 0; nt < 4; nt++) {
                const int cu = c0 + wc * 32 + nt * 8 + (l & 3) * 2;
                const size_t idx0 = (size_t)r0 * (Mq * Uq) + cu;
                const size_t idx8 = idx0 + 8 * (Mq * Uq);
                *(float2*)&g_alpha[idx0] = make_float2(acc[rt][nt][0], acc[rt][nt][1]);
                *(float2*)&g_alpha[idx8] = make_float2(acc[rt][nt][2], acc[rt][nt][3]);
            }
        }
    } else {
        __syncthreads();
        float* cs = (float*)ps;
#pragma unroll
        for (int rt = 0; rt < 2; rt++) {
            const int r0 = wr * 32 + rt * 16 + (l >> 2);
#pragma unroll
            for (int nt = 0; nt < 4; nt++) {
                const int u = wc * 32 + nt * 8 + (l & 3) * 2;
                *(float2*)&cs[r0 * CS + u] = make_float2(acc[rt][nt][0], acc[rt][nt][1]);
                *(float2*)&cs[(r0 + 8) * CS + u] = make_float2(acc[rt][nt][2], acc[rt][nt][3]);
            }
        }
        __syncthreads();
        const int b   = n0 >> 11;
        const int nin = n0 & 2047;
        const int u  = tid >> 2;
        const int nq = tid & 3;
#pragma unroll
        for (int it = 0; it < 8; it++) {
            int n = nq * 4 + it * 16;
            float v0 = cs[(n + 0) * CS + u], v1 = cs[(n + 1) * CS + u];
            float v2 = cs[(n + 2) * CS + u], v3 = cs[(n + 3) * CS + u];
            unsigned h01 = cvt_bf16x2(v0, v1), h23 = cvt_bf16x2(v2, v3);
            unsigned l01 = cvt_bf16x2(v0 - bf_lo_f(h01), v1 - bf_hi_f(h01));
            unsigned l23 = cvt_bf16x2(v2 - bf_lo_f(h23), v3 - bf_hi_f(h23));
            size_t idx = (size_t)(b * Uq + u) * Nq + nin + n;
            *(uint2*)&g_bTh[idx] = make_uint2(h01, h23);
            *(uint2*)&g_bTl[idx] = make_uint2(l01, l23);
        }
    }
}

// ---------------------------------------------------------------------------
// Kernel B (main): JC=64, 2-buffer ring, mma/STS/LDG interleaved per k-step,
// cp.async for B, XOR-swizzled j-major A (SAJ=256).
// ---------------------------------------------------------------------------
__global__ void __launch_bounds__(256, 2) multigraph_mma_kernel(
        const float* __restrict__ graph,
        float* __restrict__ out) {
    extern __shared__ __align__(16) char smem[];
    const unsigned sb = smem_u32(smem);

    const int tid = threadIdx.x;
    const int l = tid & 31;
    const int w = tid >> 5;
    const int wr = w >> 1;                   // 0..3 (32 rows)
    const int wc = w & 1;                    // 0..1 (32 u)

    const int rt0 = blockIdx.x * 128;        // global A' row base
    const int b   = blockIdx.y;
    const int i0  = rt0 >> 3;

    // A staging: lane pair covers (jp, mq); thread covers 8 il in 2 halves
    const int mq  = tid & 1;
    const int jp  = (tid >> 1) & 63;         // 0..63
    const int ilg = tid >> 7;                // 0..1
    const int jp15 = jp & 15;
    // B cp.async mapping
    const int bu0 = tid >> 3;                // 0..31
    const int bjq = tid & 7;

    float acc[2][4][4];
#pragma unroll
    for (int rt = 0; rt < 2; rt++)
#pragma unroll
        for (int nt = 0; nt < 4; nt++)
#pragma unroll
            for (int k = 0; k < 4; k++) acc[rt][nt][k] = 0.f;

    // ldmatrix lane constants
    const int jl15 = (l & 7) + ((l >> 4) & 1) * 8;   // j within 16-group
    const int cpart = (l >> 3) & 1;                   // 8-row subgroup
    const unsigned bRow = (unsigned)(wc * 32 + (l & 7) + ((l >> 4) & 1) * 8) * SBJ
                        + (unsigned)(cpart * 16);

    const size_t gbase = ((size_t)b * Nq + i0) * Nq * Mq;
    const size_t bTb = (size_t)b * Uq * Nq;

    float4 av[4];

    auto ldgA = [&](int s, int h) {
        const int j0 = s * JC;
#pragma unroll
        for (int c = 0; c < 4; c++) {
            int il = (h * 4 + c) * 2 + ilg;
            av[c] = *(const float4*)(graph + gbase
                        + ((size_t)il * Nq + j0 + jp) * Mq + mq * 4);
        }
    };
    auto stsA = [&](int p, int h) {
        char* buf = smem + p * BUF_SZ;
#pragma unroll
        for (int c = 0; c < 4; c++) {
            int il = (h * 4 + c) * 2 + ilg;      // chunk index 0..15
            const float* v = (const float*)&av[c];
            unsigned h0 = cvt_bf16x2(v[0], v[1]);
            unsigned h1 = cvt_bf16x2(v[2], v[3]);
            unsigned l0 = cvt_bf16x2(v[0] - bf_lo_f(h0), v[1] - bf_hi_f(h0));
            unsigned l1 = cvt_bf16x2(v[2] - bf_lo_f(h1), v[3] - bf_hi_f(h1));
            unsigned off = (unsigned)jp * SAJ + (unsigned)((il ^ jp15) << 4)
                         + (unsigned)(mq * 8);
            *(uint2*)(buf + AH_OFF + off) = make_uint2(h0, h1);
            *(uint2*)(buf + AL_OFF + off) = make_uint2(l0, l1);
        }
    };
    auto cpaB = [&](int s, int p) {
        const int j0 = s * JC;
        const unsigned dbase = sb + (unsigned)p * BUF_SZ;
#pragma unroll
        for (int it = 0; it < 2; it++) {
            int u = bu0 + it * 32;
            size_t src = bTb + (size_t)u * Nq + j0 + bjq * 8;
            unsigned doff = (unsigned)u * SBJ + bjq * 16;
            CP_ASYNC16(dbase + BH_OFF + doff, (const char*)&g_bTh[src]);
            CP_ASYNC16(dbase + BL_OFF + doff, (const char*)&g_bTl[src]);
        }
    };
    auto mmaKs = [&](int p, int ks) {
        const unsigned base = sb + (unsigned)p * BUF_SZ;
        const int jrow = jl15 + ks * 16;
        unsigned ah[2][4], al[2][4], bh[8], bl[8];
#pragma unroll
        for (int rt = 0; rt < 2; rt++) {
            int chunk = wr * 4 + rt * 2 + cpart;
            unsigned aoff = (unsigned)jrow * SAJ + (unsigned)((chunk ^ jl15) << 4);
            LDSM4T(ah[rt][0], ah[rt][1], ah[rt][2], ah[rt][3], base + AH_OFF + aoff);
            LDSM4T(al[rt][0], al[rt][1], al[rt][2], al[rt][3], base + AL_OFF + aoff);
        }
#pragma unroll
        for (int g = 0; g < 2; g++) {
            unsigned boff = bRow + (unsigned)g * 16 * SBJ + ks * 32;
            LDSM4(bh[g*4+0], bh[g*4+1], bh[g*4+2], bh[g*4+3], base + BH_OFF + boff);
            LDSM4(bl[g*4+0], bl[g*4+1], bl[g*4+2], bl[g*4+3], base + BL_OFF + boff);
        }
#pragma unroll
        for (int rt = 0; rt < 2; rt++)
#pragma unroll
            for (int nt = 0; nt < 4; nt++) {
                mma_bf16(acc[rt][nt], ah[rt], &bh[nt * 2]);
                mma_bf16(acc[rt][nt], al[rt], &bh[nt * 2]);
                mma_bf16(acc[rt][nt], ah[rt], &bl[nt * 2]);
            }
    };

    // prologue: stage 0 fully staged into buffer 0
    ldgA(0, 0); stsA(0, 0);
    ldgA(0, 1); stsA(0, 1);
    cpaB(0, 0); CP_COMMIT();
    CP_WAIT0();

    int pm = 0;
#pragma unroll 1
    for (int s = 0; s < NSTAGE; s++) {
        __syncthreads();                     // buf pm ready; buf pn free
        const int pn = pm ^ 1;
        const bool s1 = (s + 1 < NSTAGE);
        if (s1) ldgA(s + 1, 0);
        mmaKs(pm, 0);
        mmaKs(pm, 1);
        if (s1) {
            stsA(pn, 0);
            ldgA(s + 1, 1);
            cpaB(s + 1, pn); CP_COMMIT();
        }
        mmaKs(pm, 2);
        mmaKs(pm, 3);
        if (s1) stsA(pn, 1);
        CP_WAIT0();
        pm = pn;
    }

    // fused epilogue: + alpha, sigmoid, store
#pragma unroll
    for (int rt = 0; rt < 2; rt++) {
        const int r0 = rt0 + wr * 32 + rt * 16 + (l >> 2);
#pragma unroll
        for (int nt = 0; nt < 4; nt++) {
            const int u = wc * 32 + nt * 8 + (l & 3) * 2;
            const size_t idx0 = ((size_t)b * NM + r0) * Uq + u;
            const size_t idx8 = idx0 + 8 * Uq;
            float2 a0 = *(const float2*)&g_alpha[idx0];
            float2 a1 = *(const float2*)&g_alpha[idx8];
            float2 o0, o1;
            o0.x = 1.0f / (1.0f + __expf(-(acc[rt][nt][0] + a0.x)));
            o0.y = 1.0f / (1.0f + __expf(-(acc[rt][nt][1] + a0.y)));
            o1.x = 1.0f / (1.0f + __expf(-(acc[rt][nt][2] + a1.x)));
            o1.y = 1.0f / (1.0f + __expf(-(acc[rt][nt][3] + a1.y)));
            *(float2*)&out[idx0] = o0;
            *(float2*)&out[idx8] = o1;
        }
    }
}

// ---------------------------------------------------------------------------
extern "C" void kernel_launch(void* const* d_in, const int* in_sizes, int n_in,
                              void* d_out, int out_size) {
    const float* seq   = (const float*)d_in[0];   // (B,N,F)
    const float* graph = (const float*)d_in[1];   // (B,N,N,M)
    const float* e_w   = (const float*)d_in[2];   // (F,U)
    const float* v_w   = (const float*)d_in[3];   // (F,M,U)
    float* out = (float*)d_out;                   // (B,N,M,U)

    cudaFuncSetAttribute(precompute_mma_kernel,
                         cudaFuncAttributeMaxDynamicSharedMemorySize, SMEM_PRE);
    cudaFuncSetAttribute(multigraph_mma_kernel,
                         cudaFuncAttributeMaxDynamicSharedMemorySize, SMEM_MAIN);

    dim3 gridP(9, 32);
    precompute_mma_kernel<<<gridP, 256, SMEM_PRE>>>(seq, e_w, v_w);

    dim3 gridB(128, Bq);
    multigraph_mma_kernel<<<gridB, 256, SMEM_MAIN>>>(graph, out);
    (void)in_sizes; (void)n_in; (void)out_size;
}